// round 12
// baseline (speedup 1.0000x reference)
#include <cuda_runtime.h>
#include <cstdint>

// Problem constants
#define B_     64
#define T_     1024
#define D_     300
#define H_     512
#define G_     (4*H_)      // 2048 gate columns
#define NCTA   128         // scan CTAs: each owns 4 h-cols -> 16 gate cols
#define NTHR   256         // xproj/transpose threads
#define STHR   512         // scan threads (2 K-halves x 8 warps)
#define SEGLEN 512         // 2 scan segments
#define K4X    75          // D/4

// ---------------- device scratch (static) ----------------
__device__ float4 g_x2[(size_t)T_ * K4X * B_];        // essays transposed: [t][k4][m]
__device__ float4 g_h2[2][128 * B_];                  // h transposed: [buf][k4][m]
__device__ float  g_xp[(size_t)T_ * NCTA * B_ * 16];  // xproj[t][cc][m][16]
__device__ float  g_c [H_ * B_];                      // cell state [hcol*64+m]
__device__ float  g_hs[H_ * B_];                      // hsum
__device__ float  g_acc[B_];                          // dense partials
__device__ __align__(128) unsigned g_cnt[8 * 32];
__device__ __align__(128) unsigned g_root[32];
__device__ __align__(128) unsigned g_gen[32];

// ---------------- packed fp32 (FFMA2) ----------------
__device__ __forceinline__ void ffma2(uint64_t& d, uint64_t a, uint64_t b) {
    asm volatile("fma.rn.f32x2 %0, %1, %2, %0;" : "+l"(d) : "l"(a), "l"(b));
}
__device__ __forceinline__ uint64_t pack2(float x, float y) {
    uint64_t r; asm("mov.b64 %0, {%1, %2};" : "=l"(r) : "f"(x), "f"(y)); return r;
}
__device__ __forceinline__ float2 unpack2(uint64_t v) {
    float2 f; asm("mov.b64 {%0, %1}, %2;" : "=f"(f.x), "=f"(f.y) : "l"(v)); return f;
}
__device__ __forceinline__ void lds_v2u64(uint64_t& a, uint64_t& b, unsigned addr) {
    asm volatile("ld.shared.v2.u64 {%0, %1}, [%2];" : "=l"(a), "=l"(b) : "r"(addr));
}
// ---------------- scoped atomics / grid barrier ----------------
__device__ __forceinline__ unsigned atom_add_acqrel_gpu(unsigned* p, unsigned v) {
    unsigned r;
    asm volatile("atom.acq_rel.gpu.global.add.u32 %0, [%1], %2;" : "=r"(r) : "l"(p), "r"(v) : "memory");
    return r;
}
__device__ __forceinline__ void atom_add_release_gpu(unsigned* p, unsigned v) {
    unsigned r;
    asm volatile("atom.release.gpu.global.add.u32 %0, [%1], %2;" : "=r"(r) : "l"(p), "r"(v) : "memory");
}
__device__ __forceinline__ unsigned ld_acquire_gpu(const unsigned* p) {
    unsigned r;
    asm volatile("ld.acquire.gpu.global.u32 %0, [%1];" : "=r"(r) : "l"(p) : "memory");
    return r;
}
__device__ __forceinline__ void st_relaxed_gpu(unsigned* p, unsigned v) {
    asm volatile("st.relaxed.gpu.global.u32 [%0], %1;" :: "l"(p), "r"(v) : "memory");
}
__device__ __forceinline__ float sigm(float x)  { return 1.0f / (1.0f + __expf(-x)); }
__device__ __forceinline__ float tanh_f(float x){ return 2.0f * sigm(2.0f * x) - 1.0f; }

__device__ __forceinline__ void bar_arrive(int cc) {
    unsigned a = atom_add_acqrel_gpu(&g_cnt[(cc & 7) * 32], 1);
    if (a == (NCTA/8 - 1)) {
        unsigned r = atom_add_acqrel_gpu(&g_root[0], 1);
        if (r == 7) {
            #pragma unroll
            for (int i = 0; i < 8; i++) st_relaxed_gpu(&g_cnt[i * 32], 0);
            st_relaxed_gpu(&g_root[0], 0);
            atom_add_release_gpu(&g_gen[0], 1);
        }
    }
}

extern __shared__ float smem_dyn[];

// ============================================================================
// Phase 0: transpose essays -> g_x2[t][k4][m] float4
// ============================================================================
__global__ void __launch_bounds__(NTHR)
transpose_kernel(const float* __restrict__ essays)
{
    const int t = blockIdx.x;
    for (int idx = threadIdx.x; idx < B_ * K4X; idx += NTHR) {
        int mm = idx / K4X, kk = idx - mm * K4X;
        float4 v = __ldcs((const float4*)(essays + ((size_t)mm * T_ + t) * D_) + kk);
        g_x2[((size_t)t * K4X + kk) * B_ + mm] = v;
    }
}

// ============================================================================
// Phase A: xproj[t][cc][m][c] = x_t[m] @ Wx[:, col(cc,c)] + b  (R11-verified)
// ============================================================================
__global__ void __launch_bounds__(NTHR, 4)
xproj_kernel(const float* __restrict__ W_lstm,
             const float* __restrict__ b_lstm)
{
    float* Wsm = smem_dyn;                   // [150 k-pairs][32] = 19,200 B
    const int tid  = threadIdx.x;
    const int cc   = blockIdx.x & 127;
    const int tch  = blockIdx.x >> 7;
    const int lane = tid & 31;
    const int m    = (tid >> 5)*8 + (lane & 7);
    const int ng   = lane >> 3;
    const int q0   = ng*4;

    for (int idx = tid; idx < D_*16; idx += NTHR) {
        int k = idx >> 4, c = idx & 15;
        int col = (c >> 2) * H_ + cc*4 + (c & 3);
        Wsm[((k >> 1)*16 + c)*2 + (k & 1)] = W_lstm[(size_t)k * G_ + col];
    }
    if (blockIdx.x == 0 && tid < B_) g_acc[tid] = 0.0f;
    __syncthreads();

    const int colb = ng*H_ + cc*4;
    const uint64_t b0 = pack2(b_lstm[colb+0], 0.0f);
    const uint64_t b1 = pack2(b_lstm[colb+1], 0.0f);
    const uint64_t b2 = pack2(b_lstm[colb+2], 0.0f);
    const uint64_t b3 = pack2(b_lstm[colb+3], 0.0f);

    const unsigned wb = (unsigned)__cvta_generic_to_shared(Wsm);

    for (int t = tch*128; t < tch*128 + 128; t++) {
        uint64_t a0 = b0, a1 = b1, a2 = b2, a3 = b3;
        const ulonglong2* xp = (const ulonglong2*)&g_x2[(size_t)t * K4X * B_];
        #pragma unroll 5
        for (int k4 = 0; k4 < K4X; k4++) {
            ulonglong2 a = __ldcg(xp + k4*B_ + m);
            unsigned wa = wb + (unsigned)k4*256u + (unsigned)q0*8u;
            uint64_t w0, w1, w2, w3;
            lds_v2u64(w0, w1, wa);       lds_v2u64(w2, w3, wa + 16);
            ffma2(a0, w0, a.x); ffma2(a1, w1, a.x); ffma2(a2, w2, a.x); ffma2(a3, w3, a.x);
            lds_v2u64(w0, w1, wa + 128); lds_v2u64(w2, w3, wa + 144);
            ffma2(a0, w0, a.y); ffma2(a1, w1, a.y); ffma2(a2, w2, a.y); ffma2(a3, w3, a.y);
        }
        float2 v0 = unpack2(a0), v1 = unpack2(a1), v2 = unpack2(a2), v3 = unpack2(a3);
        float* dst = &g_xp[(((size_t)t*NCTA + cc)*B_ + m)*16 + q0];
        *(float4*)dst = make_float4(v0.x+v0.y, v1.x+v1.y, v2.x+v2.y, v3.x+v3.y);
    }
}

// ============================================================================
// Phase B: scan segment [t0, t0+SEGLEN). 128 CTAs x 512 threads.
// K split across 2 thread-halves (warps 0-7: k<256, warps 8-15: k>=256):
// per-thread serial chain halves, 4 warps/SMSP hide load latency.
// ============================================================================
__global__ void __launch_bounds__(STHR, 1)
lstm_scan_kernel(const float* __restrict__ W_lstm,
                 const float* __restrict__ W_dense,
                 const float* __restrict__ b_dense,
                 float* __restrict__ out,
                 int t0)
{
    float* Wsm  = smem_dyn;             // [256 k-pairs][32] = 32,768 B
    float* exch = smem_dyn + 256*32;    // [db][khalf][16][65] = 2*2*16*65 floats

    const int tid   = threadIdx.x;
    const int cc    = blockIdx.x;
    const int w     = tid >> 5;
    const int lane  = tid & 31;
    const int kh    = w >> 3;            // K-half 0/1
    const int m     = ((w & 7) << 3) + (lane & 7);
    const int ng    = lane >> 3;
    const int q0    = ng*4;
    const int t1    = t0 + SEGLEN;
    const bool last = (t1 == T_);

    for (int idx = tid; idx < H_*16; idx += STHR) {
        int k = idx >> 4, c = idx & 15;
        int col = (c >> 2) * H_ + cc*4 + (c & 3);
        Wsm[((k >> 1)*16 + c)*2 + (k & 1)] = W_lstm[(size_t)(D_ + k) * G_ + col];
    }

    const int hcol = cc*4 + ng;
    const int sidx = hcol*B_ + m;

    float c_st = 0.0f, hsum = 0.0f;
    if (kh == 0) {
        if (t0 == 0) {
            if (ng == 0) g_h2[0][(cc << 6) + m] = make_float4(0.f, 0.f, 0.f, 0.f);
        } else {
            c_st = g_c[sidx]; hsum = g_hs[sidx];
        }
    }

    const unsigned wbase = (unsigned)__cvta_generic_to_shared(Wsm);
    const int k4base = kh << 6;          // 0 or 64

    __shared__ unsigned s_gen;
    if (tid == 0) s_gen = ld_acquire_gpu(&g_gen[0]);
    __syncthreads();
    const unsigned base = s_gen;

    if (tid == 0) bar_arrive(cc);        // entry: init state published

    for (int t = t0; t < t1; t++) {
        // prefetch xproj (independent of barrier)
        float4 xp4;
        if (kh == 0)
            xp4 = __ldcg((const float4*)&g_xp[(((size_t)t*NCTA + cc)*B_ + m)*16 + q0]);

        const unsigned target = base + (unsigned)(t - t0 + 1);
        if (tid == 0) {
            while ((int)(ld_acquire_gpu(&g_gen[0]) - target) < 0) { }
        }
        __syncthreads();

        // H-phase (this thread's K-half): gates += h_{t-1}[k-half] @ Wh
        uint64_t a0 = 0ull, a1 = 0ull, a2 = 0ull, a3 = 0ull;
        const ulonglong2* hb = (const ulonglong2*)g_h2[t & 1];
        #pragma unroll 16
        for (int i = 0; i < 64; i++) {
            int k4 = k4base + i;
            ulonglong2 a = __ldcg(hb + (k4 << 6) + m);
            unsigned wa = wbase + (unsigned)k4*256u + (unsigned)q0*8u;
            uint64_t w0, w1, w2, w3;
            lds_v2u64(w0, w1, wa);       lds_v2u64(w2, w3, wa + 16);
            ffma2(a0, w0, a.x); ffma2(a1, w1, a.x); ffma2(a2, w2, a.x); ffma2(a3, w3, a.x);
            lds_v2u64(w0, w1, wa + 128); lds_v2u64(w2, w3, wa + 144);
            ffma2(a0, w0, a.y); ffma2(a1, w1, a.y); ffma2(a2, w2, a.y); ffma2(a3, w3, a.y);
        }

        // write partials: ex[db][kh][c][m]
        float* ex = exch + ((t & 1) * 2 + kh) * (16*65);
        float2 v0 = unpack2(a0), v1 = unpack2(a1), v2 = unpack2(a2), v3 = unpack2(a3);
        ex[(q0+0)*65 + m] = v0.x + v0.y;
        ex[(q0+1)*65 + m] = v1.x + v1.y;
        ex[(q0+2)*65 + m] = v2.x + v2.y;
        ex[(q0+3)*65 + m] = v3.x + v3.y;
        __syncthreads();

        if (kh == 0) {
            const float* exA = exch + ((t & 1) * 2 + 0) * (16*65);
            const float* exB = exch + ((t & 1) * 2 + 1) * (16*65);
            float gi = exA[(0*4 + ng)*65 + m] + exB[(0*4 + ng)*65 + m] + xp4.x*0.f;
            // gate order: xproj columns c map 1:1 to exchange cols; add xp per gate
            gi = exA[(0*4 + ng)*65 + m] + exB[(0*4 + ng)*65 + m];
            float gj = exA[(1*4 + ng)*65 + m] + exB[(1*4 + ng)*65 + m];
            float gf = exA[(2*4 + ng)*65 + m] + exB[(2*4 + ng)*65 + m];
            float go = exA[(3*4 + ng)*65 + m] + exB[(3*4 + ng)*65 + m];
            // xp4 holds cols q0..q0+3 (this thread's columns) — exchange them too:
            // simpler: xproj was added per-column by the owning thread; do that instead.
            (void)gi; (void)gj; (void)gf; (void)go;
        }
        // NOTE: xproj must be added per exchange column by its owner before reading.
        // Correction: kh==0 threads add xp4 into exA before the sum (done above via
        // a second pass). To keep one pass, we instead fold xp into exA at write time:
        __syncthreads();
        if (kh == 0) {
            float* exA = exch + ((t & 1) * 2 + 0) * (16*65);
            exA[(q0+0)*65 + m] += xp4.x;
            exA[(q0+1)*65 + m] += xp4.y;
            exA[(q0+2)*65 + m] += xp4.z;
            exA[(q0+3)*65 + m] += xp4.w;
        }
        __syncthreads();

        float nh = 0.0f;
        if (kh == 0) {
            const float* exA = exch + ((t & 1) * 2 + 0) * (16*65);
            const float* exB = exch + ((t & 1) * 2 + 1) * (16*65);
            float gi = exA[(0*4 + ng)*65 + m] + exB[(0*4 + ng)*65 + m];
            float gj = exA[(1*4 + ng)*65 + m] + exB[(1*4 + ng)*65 + m];
            float gf = exA[(2*4 + ng)*65 + m] + exB[(2*4 + ng)*65 + m];
            float go = exA[(3*4 + ng)*65 + m] + exB[(3*4 + ng)*65 + m];

            float nc = c_st * sigm(gf + 1.0f) + sigm(gi) * tanh_f(gj);
            nh = tanh_f(nc) * sigm(go);
            c_st = nc;
            hsum += nh;

            float s1 = __shfl_sync(0xffffffffu, nh, (lane & 7) + 8);
            float s2 = __shfl_sync(0xffffffffu, nh, (lane & 7) + 16);
            float s3 = __shfl_sync(0xffffffffu, nh, (lane & 7) + 24);
            if (ng == 0)
                g_h2[(t+1) & 1][(cc << 6) + m] = make_float4(nh, s1, s2, s3);
        }
        __syncthreads();   // h stores program-ordered before release-arrive

        if (t < t1 - 1) {
            if (tid == 0) bar_arrive(cc);
        }
    }

    if (kh == 0) {
        if (!last) {
            g_c[sidx]  = c_st;
            g_hs[sidx] = hsum;
        } else {
            float part = hsum * (1.0f / (float)T_) * W_dense[hcol];
            part += __shfl_xor_sync(0xffffffffu, part, 8);
            part += __shfl_xor_sync(0xffffffffu, part, 16);
            if (lane < 8) atomicAdd(&g_acc[m], part);
        }
    }
    if (!last) return;

    __syncthreads();
    if (tid == 0) bar_arrive(cc);        // final round: partials published

    if (cc == 0) {
        const unsigned ft = base + (unsigned)SEGLEN + 1u;
        if (tid == 0) {
            while ((int)(ld_acquire_gpu(&g_gen[0]) - ft) < 0) { }
        }
        __syncthreads();
        if (tid < B_) {
            float a = __ldcg(&g_acc[tid]) + b_dense[0];
            out[tid] = 1.0f / (1.0f + expf(-a));
        }
    }
}

extern "C" void kernel_launch(void* const* d_in, const int* in_sizes, int n_in,
                              void* d_out, int out_size)
{
    const float* essays  = (const float*)d_in[0];
    const float* W_lstm  = (const float*)d_in[1];
    const float* b_lstm  = (const float*)d_in[2];
    const float* W_dense = (const float*)d_in[3];
    const float* b_dense = (const float*)d_in[4];
    float* out = (float*)d_out;

    const int smem_xp   = 150*32 * (int)sizeof(float);                 // 19,200 B
    const int smem_scan = (256*32 + 4*16*65) * (int)sizeof(float);     // 49,408 B
    cudaFuncSetAttribute(xproj_kernel,
                         cudaFuncAttributeMaxDynamicSharedMemorySize, smem_xp);
    cudaFuncSetAttribute(lstm_scan_kernel,
                         cudaFuncAttributeMaxDynamicSharedMemorySize, smem_scan);

    transpose_kernel<<<T_, NTHR>>>(essays);
    xproj_kernel<<<1024, NTHR, smem_xp>>>(W_lstm, b_lstm);
    lstm_scan_kernel<<<NCTA, STHR, smem_scan>>>(W_lstm, W_dense, b_dense, out, 0);
    lstm_scan_kernel<<<NCTA, STHR, smem_scan>>>(W_lstm, W_dense, b_dense, out, SEGLEN);
}

// round 13
// speedup vs baseline: 1.5850x; 1.5850x over previous
#include <cuda_runtime.h>
#include <cstdint>

// Problem constants
#define B_     64
#define T_     1024
#define D_     300
#define H_     512
#define G_     (4*H_)      // 2048 gate columns
#define NCTA   128         // scan CTAs: each owns 4 h-cols -> 16 gate cols
#define NTHR   256         // xproj/transpose threads
#define STHR   512         // scan threads (2 K-halves x 8 warps)
#define SEGLEN 512         // 2 scan segments
#define K4X    75          // D/4

// ---------------- device scratch (static) ----------------
__device__ float4 g_x2[(size_t)T_ * K4X * B_];        // essays transposed: [t][k4][m]
__device__ float4 g_h2[2][128 * B_];                  // h transposed: [buf][k4][m]
__device__ float  g_xp[(size_t)T_ * NCTA * B_ * 16];  // xproj[t][cc][m][16]
__device__ float  g_c [H_ * B_];                      // cell state [hcol*64+m]
__device__ float  g_hs[H_ * B_];                      // hsum
__device__ float  g_acc[B_];                          // dense partials
__device__ __align__(128) unsigned g_cnt[8 * 32];
__device__ __align__(128) unsigned g_root[32];
__device__ __align__(128) unsigned g_gen[32];

// ---------------- packed fp32 (FFMA2) ----------------
__device__ __forceinline__ void ffma2(uint64_t& d, uint64_t a, uint64_t b) {
    asm volatile("fma.rn.f32x2 %0, %1, %2, %0;" : "+l"(d) : "l"(a), "l"(b));
}
__device__ __forceinline__ uint64_t pack2(float x, float y) {
    uint64_t r; asm("mov.b64 %0, {%1, %2};" : "=l"(r) : "f"(x), "f"(y)); return r;
}
__device__ __forceinline__ float2 unpack2(uint64_t v) {
    float2 f; asm("mov.b64 {%0, %1}, %2;" : "=f"(f.x), "=f"(f.y) : "l"(v)); return f;
}
__device__ __forceinline__ void lds_v2u64(uint64_t& a, uint64_t& b, unsigned addr) {
    asm volatile("ld.shared.v2.u64 {%0, %1}, [%2];" : "=l"(a), "=l"(b) : "r"(addr));
}
// ---------------- scoped atomics / grid barrier ----------------
__device__ __forceinline__ unsigned atom_add_acqrel_gpu(unsigned* p, unsigned v) {
    unsigned r;
    asm volatile("atom.acq_rel.gpu.global.add.u32 %0, [%1], %2;" : "=r"(r) : "l"(p), "r"(v) : "memory");
    return r;
}
__device__ __forceinline__ void atom_add_release_gpu(unsigned* p, unsigned v) {
    unsigned r;
    asm volatile("atom.release.gpu.global.add.u32 %0, [%1], %2;" : "=r"(r) : "l"(p), "r"(v) : "memory");
}
__device__ __forceinline__ unsigned ld_acquire_gpu(const unsigned* p) {
    unsigned r;
    asm volatile("ld.acquire.gpu.global.u32 %0, [%1];" : "=r"(r) : "l"(p) : "memory");
    return r;
}
__device__ __forceinline__ void st_relaxed_gpu(unsigned* p, unsigned v) {
    asm volatile("st.relaxed.gpu.global.u32 [%0], %1;" :: "l"(p), "r"(v) : "memory");
}
__device__ __forceinline__ float sigm(float x)  { return 1.0f / (1.0f + __expf(-x)); }
__device__ __forceinline__ float tanh_f(float x){ return 2.0f * sigm(2.0f * x) - 1.0f; }

__device__ __forceinline__ void bar_arrive(int cc) {
    unsigned a = atom_add_acqrel_gpu(&g_cnt[(cc & 7) * 32], 1);
    if (a == (NCTA/8 - 1)) {
        unsigned r = atom_add_acqrel_gpu(&g_root[0], 1);
        if (r == 7) {
            #pragma unroll
            for (int i = 0; i < 8; i++) st_relaxed_gpu(&g_cnt[i * 32], 0);
            st_relaxed_gpu(&g_root[0], 0);
            atom_add_release_gpu(&g_gen[0], 1);
        }
    }
}

extern __shared__ float smem_dyn[];

// ============================================================================
// Phase 0: transpose essays -> g_x2[t][k4][m] float4   (R11-verified)
// ============================================================================
__global__ void __launch_bounds__(NTHR)
transpose_kernel(const float* __restrict__ essays)
{
    const int t = blockIdx.x;
    for (int idx = threadIdx.x; idx < B_ * K4X; idx += NTHR) {
        int mm = idx / K4X, kk = idx - mm * K4X;
        float4 v = __ldcs((const float4*)(essays + ((size_t)mm * T_ + t) * D_) + kk);
        g_x2[((size_t)t * K4X + kk) * B_ + mm] = v;
    }
}

// ============================================================================
// Phase A: xproj[t][cc][m][c] = x_t[m] @ Wx[:, col(cc,c)] + b  (R11-verified)
// ============================================================================
__global__ void __launch_bounds__(NTHR, 4)
xproj_kernel(const float* __restrict__ W_lstm,
             const float* __restrict__ b_lstm)
{
    float* Wsm = smem_dyn;                   // [150 k-pairs][32] = 19,200 B
    const int tid  = threadIdx.x;
    const int cc   = blockIdx.x & 127;
    const int tch  = blockIdx.x >> 7;
    const int lane = tid & 31;
    const int m    = (tid >> 5)*8 + (lane & 7);
    const int ng   = lane >> 3;
    const int q0   = ng*4;

    for (int idx = tid; idx < D_*16; idx += NTHR) {
        int k = idx >> 4, c = idx & 15;
        int col = (c >> 2) * H_ + cc*4 + (c & 3);
        Wsm[((k >> 1)*16 + c)*2 + (k & 1)] = W_lstm[(size_t)k * G_ + col];
    }
    if (blockIdx.x == 0 && tid < B_) g_acc[tid] = 0.0f;
    __syncthreads();

    const int colb = ng*H_ + cc*4;
    const uint64_t b0 = pack2(b_lstm[colb+0], 0.0f);
    const uint64_t b1 = pack2(b_lstm[colb+1], 0.0f);
    const uint64_t b2 = pack2(b_lstm[colb+2], 0.0f);
    const uint64_t b3 = pack2(b_lstm[colb+3], 0.0f);

    const unsigned wb = (unsigned)__cvta_generic_to_shared(Wsm);

    for (int t = tch*128; t < tch*128 + 128; t++) {
        uint64_t a0 = b0, a1 = b1, a2 = b2, a3 = b3;
        const ulonglong2* xp = (const ulonglong2*)&g_x2[(size_t)t * K4X * B_];
        #pragma unroll 5
        for (int k4 = 0; k4 < K4X; k4++) {
            ulonglong2 a = __ldcg(xp + k4*B_ + m);
            unsigned wa = wb + (unsigned)k4*256u + (unsigned)q0*8u;
            uint64_t w0, w1, w2, w3;
            lds_v2u64(w0, w1, wa);       lds_v2u64(w2, w3, wa + 16);
            ffma2(a0, w0, a.x); ffma2(a1, w1, a.x); ffma2(a2, w2, a.x); ffma2(a3, w3, a.x);
            lds_v2u64(w0, w1, wa + 128); lds_v2u64(w2, w3, wa + 144);
            ffma2(a0, w0, a.y); ffma2(a1, w1, a.y); ffma2(a2, w2, a.y); ffma2(a3, w3, a.y);
        }
        float2 v0 = unpack2(a0), v1 = unpack2(a1), v2 = unpack2(a2), v3 = unpack2(a3);
        float* dst = &g_xp[(((size_t)t*NCTA + cc)*B_ + m)*16 + q0];
        *(float4*)dst = make_float4(v0.x+v0.y, v1.x+v1.y, v2.x+v2.y, v3.x+v3.y);
    }
}

// ============================================================================
// Phase B: scan segment [t0, t0+SEGLEN). 128 CTAs x 512 threads.
// K split across 2 warp-halves; CLEAN epilogue: exactly 3 syncthreads/step.
// ============================================================================
__global__ void __launch_bounds__(STHR, 1)
lstm_scan_kernel(const float* __restrict__ W_lstm,
                 const float* __restrict__ W_dense,
                 const float* __restrict__ b_dense,
                 float* __restrict__ out,
                 int t0)
{
    float* Wsm  = smem_dyn;             // [256 k-pairs][32] = 32,768 B
    float* exch = smem_dyn + 256*32;    // [kh][16][65] partials (2 buffers)

    const int tid   = threadIdx.x;
    const int cc    = blockIdx.x;
    const int w     = tid >> 5;
    const int lane  = tid & 31;
    const int kh    = w >> 3;            // K-half 0/1
    const int m     = ((w & 7) << 3) + (lane & 7);
    const int ng    = lane >> 3;
    const int q0    = ng*4;
    const int t1    = t0 + SEGLEN;
    const bool last = (t1 == T_);

    for (int idx = tid; idx < H_*16; idx += STHR) {
        int k = idx >> 4, c = idx & 15;
        int col = (c >> 2) * H_ + cc*4 + (c & 3);
        Wsm[((k >> 1)*16 + c)*2 + (k & 1)] = W_lstm[(size_t)(D_ + k) * G_ + col];
    }

    const int hcol = cc*4 + ng;
    const int sidx = hcol*B_ + m;

    float c_st = 0.0f, hsum = 0.0f;
    if (kh == 0) {
        if (t0 == 0) {
            if (ng == 0) g_h2[0][(cc << 6) + m] = make_float4(0.f, 0.f, 0.f, 0.f);
        } else {
            c_st = g_c[sidx]; hsum = g_hs[sidx];
        }
    }

    const unsigned wbase = (unsigned)__cvta_generic_to_shared(Wsm);
    const int k4base = kh << 6;          // 0 or 64
    float* exMine = exch + kh * (16*65);
    const float* exA = exch;
    const float* exB = exch + 16*65;

    __shared__ unsigned s_gen;
    if (tid == 0) s_gen = ld_acquire_gpu(&g_gen[0]);
    __syncthreads();
    const unsigned base = s_gen;

    if (tid == 0) bar_arrive(cc);        // entry: init state published

    for (int t = t0; t < t1; t++) {
        // prefetch xproj (independent of barrier); kh0 only
        float4 xp4 = make_float4(0.f, 0.f, 0.f, 0.f);
        if (kh == 0)
            xp4 = __ldcg((const float4*)&g_xp[(((size_t)t*NCTA + cc)*B_ + m)*16 + q0]);

        const unsigned target = base + (unsigned)(t - t0 + 1);
        if (tid == 0) {
            while ((int)(ld_acquire_gpu(&g_gen[0]) - target) < 0) { }
        }
        __syncthreads();                 // sync #1: h_{t-1} visible

        // GEMM over this thread's K-half
        uint64_t a0 = 0ull, a1 = 0ull, a2 = 0ull, a3 = 0ull;
        const ulonglong2* hb = (const ulonglong2*)g_h2[t & 1];
        #pragma unroll 16
        for (int i = 0; i < 64; i++) {
            int k4 = k4base + i;
            ulonglong2 a = __ldcg(hb + (k4 << 6) + m);
            unsigned wa = wbase + (unsigned)k4*256u + (unsigned)q0*8u;
            uint64_t w0, w1, w2, w3;
            lds_v2u64(w0, w1, wa);       lds_v2u64(w2, w3, wa + 16);
            ffma2(a0, w0, a.x); ffma2(a1, w1, a.x); ffma2(a2, w2, a.x); ffma2(a3, w3, a.x);
            lds_v2u64(w0, w1, wa + 128); lds_v2u64(w2, w3, wa + 144);
            ffma2(a0, w0, a.y); ffma2(a1, w1, a.y); ffma2(a2, w2, a.y); ffma2(a3, w3, a.y);
        }

        // single-pass partial write; kh0 folds xproj in here
        float2 v0 = unpack2(a0), v1 = unpack2(a1), v2 = unpack2(a2), v3 = unpack2(a3);
        exMine[(q0+0)*65 + m] = v0.x + v0.y + xp4.x;
        exMine[(q0+1)*65 + m] = v1.x + v1.y + xp4.y;
        exMine[(q0+2)*65 + m] = v2.x + v2.y + xp4.z;
        exMine[(q0+3)*65 + m] = v3.x + v3.y + xp4.w;
        __syncthreads();                 // sync #2: partials complete

        if (kh == 0) {
            float gi = exA[(0*4 + ng)*65 + m] + exB[(0*4 + ng)*65 + m];
            float gj = exA[(1*4 + ng)*65 + m] + exB[(1*4 + ng)*65 + m];
            float gf = exA[(2*4 + ng)*65 + m] + exB[(2*4 + ng)*65 + m];
            float go = exA[(3*4 + ng)*65 + m] + exB[(3*4 + ng)*65 + m];

            float nc = c_st * sigm(gf + 1.0f) + sigm(gi) * tanh_f(gj);
            float nh = tanh_f(nc) * sigm(go);
            c_st = nc;
            hsum += nh;

            float s1 = __shfl_sync(0xffffffffu, nh, (lane & 7) + 8);
            float s2 = __shfl_sync(0xffffffffu, nh, (lane & 7) + 16);
            float s3 = __shfl_sync(0xffffffffu, nh, (lane & 7) + 24);
            if (ng == 0)
                g_h2[(t+1) & 1][(cc << 6) + m] = make_float4(nh, s1, s2, s3);
        }
        __syncthreads();                 // sync #3: h stores + exch reads done

        if (t < t1 - 1) {
            if (tid == 0) bar_arrive(cc);
        }
    }

    if (kh == 0) {
        if (!last) {
            g_c[sidx]  = c_st;
            g_hs[sidx] = hsum;
        } else {
            float part = hsum * (1.0f / (float)T_) * W_dense[hcol];
            part += __shfl_xor_sync(0xffffffffu, part, 8);
            part += __shfl_xor_sync(0xffffffffu, part, 16);
            if (lane < 8) atomicAdd(&g_acc[m], part);
        }
    }
    if (!last) return;

    __syncthreads();
    if (tid == 0) bar_arrive(cc);        // final round: partials published

    if (cc == 0) {
        const unsigned ft = base + (unsigned)SEGLEN + 1u;
        if (tid == 0) {
            while ((int)(ld_acquire_gpu(&g_gen[0]) - ft) < 0) { }
        }
        __syncthreads();
        if (tid < B_) {
            float a = __ldcg(&g_acc[tid]) + b_dense[0];
            out[tid] = 1.0f / (1.0f + expf(-a));
        }
    }
}

extern "C" void kernel_launch(void* const* d_in, const int* in_sizes, int n_in,
                              void* d_out, int out_size)
{
    const float* essays  = (const float*)d_in[0];
    const float* W_lstm  = (const float*)d_in[1];
    const float* b_lstm  = (const float*)d_in[2];
    const float* W_dense = (const float*)d_in[3];
    const float* b_dense = (const float*)d_in[4];
    float* out = (float*)d_out;

    const int smem_xp   = 150*32 * (int)sizeof(float);                 // 19,200 B
    const int smem_scan = (256*32 + 2*16*65) * (int)sizeof(float);     // 41,088 B
    cudaFuncSetAttribute(xproj_kernel,
                         cudaFuncAttributeMaxDynamicSharedMemorySize, smem_xp);
    cudaFuncSetAttribute(lstm_scan_kernel,
                         cudaFuncAttributeMaxDynamicSharedMemorySize, smem_scan);

    transpose_kernel<<<T_, NTHR>>>(essays);
    xproj_kernel<<<1024, NTHR, smem_xp>>>(W_lstm, b_lstm);
    lstm_scan_kernel<<<NCTA, STHR, smem_scan>>>(W_lstm, W_dense, b_dense, out, 0);
    lstm_scan_kernel<<<NCTA, STHR, smem_scan>>>(W_lstm, W_dense, b_dense, out, SEGLEN);
}

// round 14
// speedup vs baseline: 1.8376x; 1.1593x over previous
#include <cuda_runtime.h>
#include <cstdint>

// Problem constants
#define B_     64
#define T_     1024
#define D_     300
#define H_     512
#define G_     (4*H_)      // 2048 gate columns
#define NCTA   128         // scan CTAs: each owns 4 h-cols -> 16 gate cols
#define NTHR   256         // xproj/transpose threads
#define STHR   512         // scan threads: 4 K-quarters x 4 warps
#define SEGLEN 512         // 2 scan segments
#define K4X    75          // D/4
#define EXS    20          // exchange row stride (floats), keeps 16B alignment

// ---------------- device scratch (static) ----------------
__device__ float4 g_x2[(size_t)T_ * K4X * B_];        // essays transposed: [t][k4][m]
__device__ float4 g_h2[2][128 * B_];                  // h transposed: [buf][k4][m]
__device__ float  g_xp[(size_t)T_ * NCTA * B_ * 16];  // xproj[t][cc][m][16]
__device__ float  g_c [H_ * B_];                      // cell state [hcol*64+m]
__device__ float  g_hs[H_ * B_];                      // hsum
__device__ float  g_acc[B_];                          // dense partials
__device__ __align__(128) unsigned g_cnt[8 * 32];
__device__ __align__(128) unsigned g_root[32];
__device__ __align__(128) unsigned g_gen[32];

// ---------------- packed fp32 (FFMA2) ----------------
__device__ __forceinline__ void ffma2(uint64_t& d, uint64_t a, uint64_t b) {
    asm volatile("fma.rn.f32x2 %0, %1, %2, %0;" : "+l"(d) : "l"(a), "l"(b));
}
__device__ __forceinline__ uint64_t pack2(float x, float y) {
    uint64_t r; asm("mov.b64 %0, {%1, %2};" : "=l"(r) : "f"(x), "f"(y)); return r;
}
__device__ __forceinline__ float2 unpack2(uint64_t v) {
    float2 f; asm("mov.b64 {%0, %1}, %2;" : "=f"(f.x), "=f"(f.y) : "l"(v)); return f;
}
__device__ __forceinline__ void lds_v2u64(uint64_t& a, uint64_t& b, unsigned addr) {
    asm volatile("ld.shared.v2.u64 {%0, %1}, [%2];" : "=l"(a), "=l"(b) : "r"(addr));
}
// ---------------- scoped atomics / grid barrier ----------------
__device__ __forceinline__ unsigned atom_add_acqrel_gpu(unsigned* p, unsigned v) {
    unsigned r;
    asm volatile("atom.acq_rel.gpu.global.add.u32 %0, [%1], %2;" : "=r"(r) : "l"(p), "r"(v) : "memory");
    return r;
}
__device__ __forceinline__ void atom_add_release_gpu(unsigned* p, unsigned v) {
    unsigned r;
    asm volatile("atom.release.gpu.global.add.u32 %0, [%1], %2;" : "=r"(r) : "l"(p), "r"(v) : "memory");
}
__device__ __forceinline__ unsigned ld_acquire_gpu(const unsigned* p) {
    unsigned r;
    asm volatile("ld.acquire.gpu.global.u32 %0, [%1];" : "=r"(r) : "l"(p) : "memory");
    return r;
}
__device__ __forceinline__ void st_relaxed_gpu(unsigned* p, unsigned v) {
    asm volatile("st.relaxed.gpu.global.u32 [%0], %1;" :: "l"(p), "r"(v) : "memory");
}
__device__ __forceinline__ float sigm(float x)  { return 1.0f / (1.0f + __expf(-x)); }
__device__ __forceinline__ float tanh_f(float x){ return 2.0f * sigm(2.0f * x) - 1.0f; }

__device__ __forceinline__ void bar_arrive(int cc) {
    unsigned a = atom_add_acqrel_gpu(&g_cnt[(cc & 7) * 32], 1);
    if (a == (NCTA/8 - 1)) {
        unsigned r = atom_add_acqrel_gpu(&g_root[0], 1);
        if (r == 7) {
            #pragma unroll
            for (int i = 0; i < 8; i++) st_relaxed_gpu(&g_cnt[i * 32], 0);
            st_relaxed_gpu(&g_root[0], 0);
            atom_add_release_gpu(&g_gen[0], 1);
        }
    }
}

extern __shared__ float smem_dyn[];

// ============================================================================
// Phase 0: transpose essays -> g_x2[t][k4][m] float4   (R11-verified)
// ============================================================================
__global__ void __launch_bounds__(NTHR)
transpose_kernel(const float* __restrict__ essays)
{
    const int t = blockIdx.x;
    for (int idx = threadIdx.x; idx < B_ * K4X; idx += NTHR) {
        int mm = idx / K4X, kk = idx - mm * K4X;
        float4 v = __ldcs((const float4*)(essays + ((size_t)mm * T_ + t) * D_) + kk);
        g_x2[((size_t)t * K4X + kk) * B_ + mm] = v;
    }
}

// ============================================================================
// Phase A: xproj[t][cc][m][c] = x_t[m] @ Wx[:, col(cc,c)] + b  (R11-verified)
// ============================================================================
__global__ void __launch_bounds__(NTHR, 4)
xproj_kernel(const float* __restrict__ W_lstm,
             const float* __restrict__ b_lstm)
{
    float* Wsm = smem_dyn;                   // [150 k-pairs][32] = 19,200 B
    const int tid  = threadIdx.x;
    const int cc   = blockIdx.x & 127;
    const int tch  = blockIdx.x >> 7;
    const int lane = tid & 31;
    const int m    = (tid >> 5)*8 + (lane & 7);
    const int ng   = lane >> 3;
    const int q0   = ng*4;

    for (int idx = tid; idx < D_*16; idx += NTHR) {
        int k = idx >> 4, c = idx & 15;
        int col = (c >> 2) * H_ + cc*4 + (c & 3);
        Wsm[((k >> 1)*16 + c)*2 + (k & 1)] = W_lstm[(size_t)k * G_ + col];
    }
    if (blockIdx.x == 0 && tid < B_) g_acc[tid] = 0.0f;
    __syncthreads();

    const int colb = ng*H_ + cc*4;
    const uint64_t b0 = pack2(b_lstm[colb+0], 0.0f);
    const uint64_t b1 = pack2(b_lstm[colb+1], 0.0f);
    const uint64_t b2 = pack2(b_lstm[colb+2], 0.0f);
    const uint64_t b3 = pack2(b_lstm[colb+3], 0.0f);

    const unsigned wb = (unsigned)__cvta_generic_to_shared(Wsm);

    for (int t = tch*128; t < tch*128 + 128; t++) {
        uint64_t a0 = b0, a1 = b1, a2 = b2, a3 = b3;
        const ulonglong2* xp = (const ulonglong2*)&g_x2[(size_t)t * K4X * B_];
        #pragma unroll 5
        for (int k4 = 0; k4 < K4X; k4++) {
            ulonglong2 a = __ldcg(xp + k4*B_ + m);
            unsigned wa = wb + (unsigned)k4*256u + (unsigned)q0*8u;
            uint64_t w0, w1, w2, w3;
            lds_v2u64(w0, w1, wa);       lds_v2u64(w2, w3, wa + 16);
            ffma2(a0, w0, a.x); ffma2(a1, w1, a.x); ffma2(a2, w2, a.x); ffma2(a3, w3, a.x);
            lds_v2u64(w0, w1, wa + 128); lds_v2u64(w2, w3, wa + 144);
            ffma2(a0, w0, a.y); ffma2(a1, w1, a.y); ffma2(a2, w2, a.y); ffma2(a3, w3, a.y);
        }
        float2 v0 = unpack2(a0), v1 = unpack2(a1), v2 = unpack2(a2), v3 = unpack2(a3);
        float* dst = &g_xp[(((size_t)t*NCTA + cc)*B_ + m)*16 + q0];
        *(float4*)dst = make_float4(v0.x+v0.y, v1.x+v1.y, v2.x+v2.y, v3.x+v3.y);
    }
}

// ============================================================================
// Phase B: scan segment [t0, t0+SEGLEN). 128 CTAs x 512 threads.
// Thread = (2 m-rows, 4 cols, K-quarter): each W LDS feeds 16 FFMA2
// -> W-LDS wavefronts halved; kernel FMA-floor-bound. 3 syncs/step.
// ============================================================================
__global__ void __launch_bounds__(STHR, 1)
lstm_scan_kernel(const float* __restrict__ W_lstm,
                 const float* __restrict__ W_dense,
                 const float* __restrict__ b_dense,
                 float* __restrict__ out,
                 int t0)
{
    float* Wsm = smem_dyn;              // [256 k-pairs][32] = 32,768 B
    float* ex  = smem_dyn + 256*32;     // 4 x [64][EXS] partials = 20,480 B

    const int tid   = threadIdx.x;
    const int cc    = blockIdx.x;
    const int w     = tid >> 5;
    const int lane  = tid & 31;
    const int kq    = w >> 2;            // K-quarter 0..3
    const int wq    = w & 3;
    const int mpl   = lane & 7;
    const int ng    = lane >> 3;
    const int q0    = ng*4;
    const int mA    = wq*8 + mpl;        // rows mA and mA+32
    const int t1    = t0 + SEGLEN;
    const bool last = (t1 == T_);

    // Wh slice pair-major (R13 layout): Wsm[k2][c*2+half]
    for (int idx = tid; idx < H_*16; idx += STHR) {
        int k = idx >> 4, c = idx & 15;
        int col = (c >> 2) * H_ + cc*4 + (c & 3);
        Wsm[((k >> 1)*16 + c)*2 + (k & 1)] = W_lstm[(size_t)(D_ + k) * G_ + col];
    }

    // reducer identity (tid < 256): same mapping as R13
    const int rm   = (tid >> 5)*8 + (lane & 7);   // valid for tid<256 (w 0..7)
    const int rng  = lane >> 3;
    const int hcol = cc*4 + rng;
    const int sidx = hcol*B_ + rm;

    float c_st = 0.0f, hsum = 0.0f;
    if (tid < 256) {
        if (t0 == 0) {
            if (rng == 0) g_h2[0][(cc << 6) + rm] = make_float4(0.f, 0.f, 0.f, 0.f);
        } else {
            c_st = g_c[sidx]; hsum = g_hs[sidx];
        }
    }

    const unsigned wbase = (unsigned)__cvta_generic_to_shared(Wsm);
    float* exk = ex + kq * (B_ * EXS);

    __shared__ unsigned s_gen;
    if (tid == 0) s_gen = ld_acquire_gpu(&g_gen[0]);
    __syncthreads();
    const unsigned base = s_gen;

    if (tid == 0) bar_arrive(cc);        // entry: init state published

    for (int t = t0; t < t1; t++) {
        // prefetch xproj for kq==0 writers (independent of barrier)
        float4 xpA = make_float4(0.f,0.f,0.f,0.f), xpB = xpA;
        if (kq == 0) {
            const float* xb = &g_xp[((size_t)t*NCTA + cc)*B_*16];
            xpA = __ldcg((const float4*)(xb + (size_t)mA*16 + q0));
            xpB = __ldcg((const float4*)(xb + (size_t)(mA+32)*16 + q0));
        }

        const unsigned target = base + (unsigned)(t - t0 + 1);
        if (tid == 0) {
            while ((int)(ld_acquire_gpu(&g_gen[0]) - target) < 0) { }
        }
        __syncthreads();                 // sync #1: h_{t-1} visible

        // GEMM over this thread's K-quarter, 2 m-rows x 4 cols
        uint64_t p0=0,p1=0,p2=0,p3=0,p4=0,p5=0,p6=0,p7=0;
        const ulonglong2* hb = (const ulonglong2*)g_h2[t & 1];
        #pragma unroll 8
        for (int i = 0; i < 32; i++) {
            int k4 = (kq << 5) + i;
            ulonglong2 aA = __ldcg(hb + (k4 << 6) + mA);
            ulonglong2 aB = __ldcg(hb + (k4 << 6) + mA + 32);
            unsigned wa = wbase + (unsigned)k4*256u + (unsigned)q0*8u;
            uint64_t w0, w1, w2, w3;
            lds_v2u64(w0, w1, wa);       lds_v2u64(w2, w3, wa + 16);
            ffma2(p0, w0, aA.x); ffma2(p1, w1, aA.x); ffma2(p2, w2, aA.x); ffma2(p3, w3, aA.x);
            ffma2(p4, w0, aB.x); ffma2(p5, w1, aB.x); ffma2(p6, w2, aB.x); ffma2(p7, w3, aB.x);
            lds_v2u64(w0, w1, wa + 128); lds_v2u64(w2, w3, wa + 144);
            ffma2(p0, w0, aA.y); ffma2(p1, w1, aA.y); ffma2(p2, w2, aA.y); ffma2(p3, w3, aA.y);
            ffma2(p4, w0, aB.y); ffma2(p5, w1, aB.y); ffma2(p6, w2, aB.y); ffma2(p7, w3, aB.y);
        }

        // write partials (kq0 folds xproj); ex[kq][m][c], float4 at c=q0
        {
            float2 u0 = unpack2(p0), u1 = unpack2(p1), u2 = unpack2(p2), u3 = unpack2(p3);
            float2 u4 = unpack2(p4), u5 = unpack2(p5), u6 = unpack2(p6), u7 = unpack2(p7);
            *(float4*)&exk[mA*EXS + q0] =
                make_float4(u0.x+u0.y+xpA.x, u1.x+u1.y+xpA.y, u2.x+u2.y+xpA.z, u3.x+u3.y+xpA.w);
            *(float4*)&exk[(mA+32)*EXS + q0] =
                make_float4(u4.x+u4.y+xpB.x, u5.x+u5.y+xpB.y, u6.x+u6.y+xpB.z, u7.x+u7.y+xpB.w);
        }
        __syncthreads();                 // sync #2: all partials complete

        if (tid < 256) {
            const float* e0 = ex;
            const float* e1 = ex + 1*(B_*EXS);
            const float* e2 = ex + 2*(B_*EXS);
            const float* e3 = ex + 3*(B_*EXS);
            int rb = rm*EXS;
            float gi = e0[rb+0*4+rng] + e1[rb+0*4+rng] + e2[rb+0*4+rng] + e3[rb+0*4+rng];
            float gj = e0[rb+1*4+rng] + e1[rb+1*4+rng] + e2[rb+1*4+rng] + e3[rb+1*4+rng];
            float gf = e0[rb+2*4+rng] + e1[rb+2*4+rng] + e2[rb+2*4+rng] + e3[rb+2*4+rng];
            float go = e0[rb+3*4+rng] + e1[rb+3*4+rng] + e2[rb+3*4+rng] + e3[rb+3*4+rng];

            float nc = c_st * sigm(gf + 1.0f) + sigm(gi) * tanh_f(gj);
            float nh = tanh_f(nc) * sigm(go);
            c_st = nc;
            hsum += nh;

            float s1 = __shfl_sync(0xffffffffu, nh, (lane & 7) + 8);
            float s2 = __shfl_sync(0xffffffffu, nh, (lane & 7) + 16);
            float s3 = __shfl_sync(0xffffffffu, nh, (lane & 7) + 24);
            if (rng == 0)
                g_h2[(t+1) & 1][(cc << 6) + rm] = make_float4(nh, s1, s2, s3);
        }
        __syncthreads();                 // sync #3: h stores + ex reads done

        if (t < t1 - 1) {
            if (tid == 0) bar_arrive(cc);
        }
    }

    if (tid < 256) {
        if (!last) {
            g_c[sidx]  = c_st;
            g_hs[sidx] = hsum;
        } else {
            float part = hsum * (1.0f / (float)T_) * W_dense[hcol];
            part += __shfl_xor_sync(0xffffffffu, part, 8);
            part += __shfl_xor_sync(0xffffffffu, part, 16);
            if (lane < 8) atomicAdd(&g_acc[rm], part);
        }
    }
    if (!last) return;

    __syncthreads();
    if (tid == 0) bar_arrive(cc);        // final round: partials published

    if (cc == 0) {
        const unsigned ft = base + (unsigned)SEGLEN + 1u;
        if (tid == 0) {
            while ((int)(ld_acquire_gpu(&g_gen[0]) - ft) < 0) { }
        }
        __syncthreads();
        if (tid < B_) {
            float a = __ldcg(&g_acc[tid]) + b_dense[0];
            out[tid] = 1.0f / (1.0f + expf(-a));
        }
    }
}

extern "C" void kernel_launch(void* const* d_in, const int* in_sizes, int n_in,
                              void* d_out, int out_size)
{
    const float* essays  = (const float*)d_in[0];
    const float* W_lstm  = (const float*)d_in[1];
    const float* b_lstm  = (const float*)d_in[2];
    const float* W_dense = (const float*)d_in[3];
    const float* b_dense = (const float*)d_in[4];
    float* out = (float*)d_out;

    const int smem_xp   = 150*32 * (int)sizeof(float);                 // 19,200 B
    const int smem_scan = (256*32 + 4*B_*EXS) * (int)sizeof(float);    // 53,248 B
    cudaFuncSetAttribute(xproj_kernel,
                         cudaFuncAttributeMaxDynamicSharedMemorySize, smem_xp);
    cudaFuncSetAttribute(lstm_scan_kernel,
                         cudaFuncAttributeMaxDynamicSharedMemorySize, smem_scan);

    transpose_kernel<<<T_, NTHR>>>(essays);
    xproj_kernel<<<1024, NTHR, smem_xp>>>(W_lstm, b_lstm);
    lstm_scan_kernel<<<NCTA, STHR, smem_scan>>>(W_lstm, W_dense, b_dense, out, 0);
    lstm_scan_kernel<<<NCTA, STHR, smem_scan>>>(W_lstm, W_dense, b_dense, out, SEGLEN);
}

// round 15
// speedup vs baseline: 1.9525x; 1.0625x over previous
#include <cuda_runtime.h>
#include <cstdint>

// Problem constants
#define B_     64
#define T_     1024
#define D_     300
#define H_     512
#define G_     (4*H_)      // 2048 gate columns
#define NCTA   128         // scan CTAs: each owns 4 h-cols -> 16 gate cols
#define NTHR   256         // xproj/transpose threads
#define STHR   512         // scan threads: 4 K-quarters x 4 warps
#define SEGLEN 512         // 2 scan segments
#define K4X    75          // D/4
#define EXS    20          // exchange row stride (floats)

// ---------------- device scratch (static) ----------------
__device__ float4 g_x2[(size_t)T_ * K4X * B_];        // essays transposed: [t][k4][m]
__device__ float4 g_h2[2][128 * B_];                  // h transposed: [buf][k4][m]
__device__ float  g_xp[(size_t)T_ * NCTA * B_ * 16];  // xproj[t][cc][m][16]
__device__ float  g_c [H_ * B_];                      // cell state [hcol*64+m]
__device__ float  g_hs[H_ * B_];                      // hsum
__device__ float  g_acc[B_];                          // dense partials
__device__ __align__(128) unsigned g_cnt[8 * 32];
__device__ __align__(128) unsigned g_root[32];
__device__ __align__(128) unsigned g_gen[32];

// ---------------- packed fp32 (FFMA2) ----------------
__device__ __forceinline__ void ffma2(uint64_t& d, uint64_t a, uint64_t b) {
    asm volatile("fma.rn.f32x2 %0, %1, %2, %0;" : "+l"(d) : "l"(a), "l"(b));
}
__device__ __forceinline__ uint64_t pack2(float x, float y) {
    uint64_t r; asm("mov.b64 %0, {%1, %2};" : "=l"(r) : "f"(x), "f"(y)); return r;
}
__device__ __forceinline__ float2 unpack2(uint64_t v) {
    float2 f; asm("mov.b64 {%0, %1}, %2;" : "=f"(f.x), "=f"(f.y) : "l"(v)); return f;
}
__device__ __forceinline__ void lds_v2u64(uint64_t& a, uint64_t& b, unsigned addr) {
    asm volatile("ld.shared.v2.u64 {%0, %1}, [%2];" : "=l"(a), "=l"(b) : "r"(addr));
}
// ---------------- scoped atomics / grid barrier ----------------
__device__ __forceinline__ unsigned atom_add_acqrel_gpu(unsigned* p, unsigned v) {
    unsigned r;
    asm volatile("atom.acq_rel.gpu.global.add.u32 %0, [%1], %2;" : "=r"(r) : "l"(p), "r"(v) : "memory");
    return r;
}
__device__ __forceinline__ void atom_add_release_gpu(unsigned* p, unsigned v) {
    unsigned r;
    asm volatile("atom.release.gpu.global.add.u32 %0, [%1], %2;" : "=r"(r) : "l"(p), "r"(v) : "memory");
}
__device__ __forceinline__ unsigned ld_acquire_gpu(const unsigned* p) {
    unsigned r;
    asm volatile("ld.acquire.gpu.global.u32 %0, [%1];" : "=r"(r) : "l"(p) : "memory");
    return r;
}
__device__ __forceinline__ void st_relaxed_gpu(unsigned* p, unsigned v) {
    asm volatile("st.relaxed.gpu.global.u32 [%0], %1;" :: "l"(p), "r"(v) : "memory");
}
__device__ __forceinline__ float sigm(float x)  { return 1.0f / (1.0f + __expf(-x)); }
__device__ __forceinline__ float tanh_f(float x){ return 2.0f * sigm(2.0f * x) - 1.0f; }

// 8 warp-arrivals per CTA per round: sub-counter target 16 CTAs x 8 = 128
__device__ __forceinline__ void bar_arrive(int cc) {
    unsigned a = atom_add_acqrel_gpu(&g_cnt[(cc & 7) * 32], 1);
    if (a == 127) {
        unsigned r = atom_add_acqrel_gpu(&g_root[0], 1);
        if (r == 7) {
            #pragma unroll
            for (int i = 0; i < 8; i++) st_relaxed_gpu(&g_cnt[i * 32], 0);
            st_relaxed_gpu(&g_root[0], 0);
            atom_add_release_gpu(&g_gen[0], 1);
        }
    }
}

extern __shared__ float smem_dyn[];

// ============================================================================
// Phase 0: transpose essays -> g_x2[t][k4][m] float4   (R11-verified)
// ============================================================================
__global__ void __launch_bounds__(NTHR)
transpose_kernel(const float* __restrict__ essays)
{
    const int t = blockIdx.x;
    for (int idx = threadIdx.x; idx < B_ * K4X; idx += NTHR) {
        int mm = idx / K4X, kk = idx - mm * K4X;
        float4 v = __ldcs((const float4*)(essays + ((size_t)mm * T_ + t) * D_) + kk);
        g_x2[((size_t)t * K4X + kk) * B_ + mm] = v;
    }
}

// ============================================================================
// Phase A: xproj[t][cc][m][c] = x_t[m] @ Wx[:, col(cc,c)] + b
// 2-row amortization: thread = (2 m-rows x 4 cols); warps split t-range.
// ============================================================================
__global__ void __launch_bounds__(NTHR, 4)
xproj_kernel(const float* __restrict__ W_lstm,
             const float* __restrict__ b_lstm)
{
    float* Wsm = smem_dyn;                   // [150 k-pairs][32] = 19,200 B
    const int tid  = threadIdx.x;
    const int cc   = blockIdx.x & 127;
    const int tch  = blockIdx.x >> 7;        // 0..7, 128 t each
    const int w    = tid >> 5;
    const int lane = tid & 31;
    const int tg   = w >> 2;                 // t-half within chunk (0/1)
    const int wm   = w & 3;
    const int mpl  = lane & 7;
    const int ng   = lane >> 3;
    const int q0   = ng*4;
    const int mA   = wm*8 + mpl;             // rows mA and mA+32

    for (int idx = tid; idx < D_*16; idx += NTHR) {
        int k = idx >> 4, c = idx & 15;
        int col = (c >> 2) * H_ + cc*4 + (c & 3);
        Wsm[((k >> 1)*16 + c)*2 + (k & 1)] = W_lstm[(size_t)k * G_ + col];
    }
    if (blockIdx.x == 0 && tid < B_) g_acc[tid] = 0.0f;
    __syncthreads();

    const int colb = ng*H_ + cc*4;
    const uint64_t b0 = pack2(b_lstm[colb+0], 0.0f);
    const uint64_t b1 = pack2(b_lstm[colb+1], 0.0f);
    const uint64_t b2 = pack2(b_lstm[colb+2], 0.0f);
    const uint64_t b3 = pack2(b_lstm[colb+3], 0.0f);

    const unsigned wb = (unsigned)__cvta_generic_to_shared(Wsm);
    const int tbeg = tch*128 + tg*64;

    for (int t = tbeg; t < tbeg + 64; t++) {
        uint64_t a0 = b0, a1 = b1, a2 = b2, a3 = b3;   // rows mA
        uint64_t a4 = b0, a5 = b1, a6 = b2, a7 = b3;   // rows mA+32
        const ulonglong2* xp = (const ulonglong2*)&g_x2[(size_t)t * K4X * B_];
        #pragma unroll 5
        for (int k4 = 0; k4 < K4X; k4++) {
            ulonglong2 aA = __ldcg(xp + k4*B_ + mA);
            ulonglong2 aB = __ldcg(xp + k4*B_ + mA + 32);
            unsigned wa = wb + (unsigned)k4*256u + (unsigned)q0*8u;
            uint64_t w0, w1, w2, w3;
            lds_v2u64(w0, w1, wa);       lds_v2u64(w2, w3, wa + 16);
            ffma2(a0, w0, aA.x); ffma2(a1, w1, aA.x); ffma2(a2, w2, aA.x); ffma2(a3, w3, aA.x);
            ffma2(a4, w0, aB.x); ffma2(a5, w1, aB.x); ffma2(a6, w2, aB.x); ffma2(a7, w3, aB.x);
            lds_v2u64(w0, w1, wa + 128); lds_v2u64(w2, w3, wa + 144);
            ffma2(a0, w0, aA.y); ffma2(a1, w1, aA.y); ffma2(a2, w2, aA.y); ffma2(a3, w3, aA.y);
            ffma2(a4, w0, aB.y); ffma2(a5, w1, aB.y); ffma2(a6, w2, aB.y); ffma2(a7, w3, aB.y);
        }
        float* dst = &g_xp[(((size_t)t*NCTA + cc)*B_)*16];
        {
            float2 u0 = unpack2(a0), u1 = unpack2(a1), u2 = unpack2(a2), u3 = unpack2(a3);
            *(float4*)(dst + (size_t)mA*16 + q0) =
                make_float4(u0.x+u0.y, u1.x+u1.y, u2.x+u2.y, u3.x+u3.y);
            float2 u4 = unpack2(a4), u5 = unpack2(a5), u6 = unpack2(a6), u7 = unpack2(a7);
            *(float4*)(dst + (size_t)(mA+32)*16 + q0) =
                make_float4(u4.x+u4.y, u5.x+u5.y, u6.x+u6.y, u7.x+u7.y);
        }
    }
}

// ============================================================================
// Phase B: scan segment [t0, t0+SEGLEN). 128 CTAs x 512 threads.
// R14 GEMM core; per-reducer-warp release-arrivals (8/CTA), 2 syncs/step.
// ============================================================================
__global__ void __launch_bounds__(STHR, 1)
lstm_scan_kernel(const float* __restrict__ W_lstm,
                 const float* __restrict__ W_dense,
                 const float* __restrict__ b_dense,
                 float* __restrict__ out,
                 int t0)
{
    float* Wsm = smem_dyn;              // [256 k-pairs][32] = 32,768 B
    float* ex  = smem_dyn + 256*32;     // 4 x [64][EXS] partials

    const int tid   = threadIdx.x;
    const int cc    = blockIdx.x;
    const int w     = tid >> 5;
    const int lane  = tid & 31;
    const int kq    = w >> 2;            // K-quarter 0..3
    const int wq    = w & 3;
    const int mpl   = lane & 7;
    const int ng    = lane >> 3;
    const int q0    = ng*4;
    const int mA    = wq*8 + mpl;        // rows mA and mA+32
    const int t1    = t0 + SEGLEN;
    const bool last = (t1 == T_);

    for (int idx = tid; idx < H_*16; idx += STHR) {
        int k = idx >> 4, c = idx & 15;
        int col = (c >> 2) * H_ + cc*4 + (c & 3);
        Wsm[((k >> 1)*16 + c)*2 + (k & 1)] = W_lstm[(size_t)(D_ + k) * G_ + col];
    }

    // reducer identity (tid < 256)
    const int rm   = (tid >> 5)*8 + (lane & 7);
    const int rng  = lane >> 3;
    const int hcol = cc*4 + rng;
    const int sidx = hcol*B_ + rm;

    float c_st = 0.0f, hsum = 0.0f;
    if (tid < 256) {
        if (t0 == 0) {
            if (rng == 0) g_h2[0][(cc << 6) + rm] = make_float4(0.f, 0.f, 0.f, 0.f);
        } else {
            c_st = g_c[sidx]; hsum = g_hs[sidx];
        }
    }

    const unsigned wbase = (unsigned)__cvta_generic_to_shared(Wsm);
    float* exk = ex + kq * (B_ * EXS);

    __shared__ unsigned s_gen;
    if (tid == 0) s_gen = ld_acquire_gpu(&g_gen[0]);
    __syncthreads();
    const unsigned base = s_gen;

    // entry arrivals: 8 reducer warps publish init state
    if (tid < 256) {
        __syncwarp();
        if (lane == 0) bar_arrive(cc);
    }

    for (int t = t0; t < t1; t++) {
        // prefetch xproj for kq==0 writers (independent of barrier)
        float4 xpA = make_float4(0.f,0.f,0.f,0.f), xpB = xpA;
        if (kq == 0) {
            const float* xb = &g_xp[((size_t)t*NCTA + cc)*B_*16];
            xpA = __ldcg((const float4*)(xb + (size_t)mA*16 + q0));
            xpB = __ldcg((const float4*)(xb + (size_t)(mA+32)*16 + q0));
        }

        const unsigned target = base + (unsigned)(t - t0 + 1);
        if (tid == 0) {
            while ((int)(ld_acquire_gpu(&g_gen[0]) - target) < 0) { }
        }
        __syncthreads();                 // sync #1: h_{t-1} visible

        // GEMM over this thread's K-quarter, 2 m-rows x 4 cols
        uint64_t p0=0,p1=0,p2=0,p3=0,p4=0,p5=0,p6=0,p7=0;
        const ulonglong2* hb = (const ulonglong2*)g_h2[t & 1];
        #pragma unroll 8
        for (int i = 0; i < 32; i++) {
            int k4 = (kq << 5) + i;
            ulonglong2 aA = __ldcg(hb + (k4 << 6) + mA);
            ulonglong2 aB = __ldcg(hb + (k4 << 6) + mA + 32);
            unsigned wa = wbase + (unsigned)k4*256u + (unsigned)q0*8u;
            uint64_t w0, w1, w2, w3;
            lds_v2u64(w0, w1, wa);       lds_v2u64(w2, w3, wa + 16);
            ffma2(p0, w0, aA.x); ffma2(p1, w1, aA.x); ffma2(p2, w2, aA.x); ffma2(p3, w3, aA.x);
            ffma2(p4, w0, aB.x); ffma2(p5, w1, aB.x); ffma2(p6, w2, aB.x); ffma2(p7, w3, aB.x);
            lds_v2u64(w0, w1, wa + 128); lds_v2u64(w2, w3, wa + 144);
            ffma2(p0, w0, aA.y); ffma2(p1, w1, aA.y); ffma2(p2, w2, aA.y); ffma2(p3, w3, aA.y);
            ffma2(p4, w0, aB.y); ffma2(p5, w1, aB.y); ffma2(p6, w2, aB.y); ffma2(p7, w3, aB.y);
        }

        // write partials (kq0 folds xproj); ex[kq][m][c]
        {
            float2 u0 = unpack2(p0), u1 = unpack2(p1), u2 = unpack2(p2), u3 = unpack2(p3);
            float2 u4 = unpack2(p4), u5 = unpack2(p5), u6 = unpack2(p6), u7 = unpack2(p7);
            *(float4*)&exk[mA*EXS + q0] =
                make_float4(u0.x+u0.y+xpA.x, u1.x+u1.y+xpA.y, u2.x+u2.y+xpA.z, u3.x+u3.y+xpA.w);
            *(float4*)&exk[(mA+32)*EXS + q0] =
                make_float4(u4.x+u4.y+xpB.x, u5.x+u5.y+xpB.y, u6.x+u6.y+xpB.z, u7.x+u7.y+xpB.w);
        }
        __syncthreads();                 // sync #2: all partials complete

        if (tid < 256) {
            const float* e0 = ex;
            const float* e1 = ex + 1*(B_*EXS);
            const float* e2 = ex + 2*(B_*EXS);
            const float* e3 = ex + 3*(B_*EXS);
            int rb = rm*EXS;
            float gi = e0[rb+0*4+rng] + e1[rb+0*4+rng] + e2[rb+0*4+rng] + e3[rb+0*4+rng];
            float gj = e0[rb+1*4+rng] + e1[rb+1*4+rng] + e2[rb+1*4+rng] + e3[rb+1*4+rng];
            float gf = e0[rb+2*4+rng] + e1[rb+2*4+rng] + e2[rb+2*4+rng] + e3[rb+2*4+rng];
            float go = e0[rb+3*4+rng] + e1[rb+3*4+rng] + e2[rb+3*4+rng] + e3[rb+3*4+rng];

            float nc = c_st * sigm(gf + 1.0f) + sigm(gi) * tanh_f(gj);
            float nh = tanh_f(nc) * sigm(go);
            c_st = nc;
            hsum += nh;

            float s1 = __shfl_sync(0xffffffffu, nh, (lane & 7) + 8);
            float s2 = __shfl_sync(0xffffffffu, nh, (lane & 7) + 16);
            float s3 = __shfl_sync(0xffffffffu, nh, (lane & 7) + 24);
            if (rng == 0)
                g_h2[(t+1) & 1][(cc << 6) + rm] = make_float4(nh, s1, s2, s3);

            // per-warp release-arrive: warp-ordered h stores published
            __syncwarp();
            if (t < t1 - 1 && lane == 0) bar_arrive(cc);
        }
        // (no sync #3: ex reuse is gated by next round's sync #1; GEMM warps
        //  finished all ex reads/writes before sync #2.)
    }

    if (tid < 256) {
        if (!last) {
            g_c[sidx]  = c_st;
            g_hs[sidx] = hsum;
        } else {
            float part = hsum * (1.0f / (float)T_) * W_dense[hcol];
            part += __shfl_xor_sync(0xffffffffu, part, 8);
            part += __shfl_xor_sync(0xffffffffu, part, 16);
            if (lane < 8) atomicAdd(&g_acc[rm], part);
            __syncwarp();
            if (lane == 0) bar_arrive(cc);   // final round: partials published
        }
    }
    if (!last) return;

    if (cc == 0) {
        const unsigned ft = base + (unsigned)SEGLEN + 1u;
        if (tid == 0) {
            while ((int)(ld_acquire_gpu(&g_gen[0]) - ft) < 0) { }
        }
        __syncthreads();
        if (tid < B_) {
            float a = __ldcg(&g_acc[tid]) + b_dense[0];
            out[tid] = 1.0f / (1.0f + expf(-a));
        }
    }
}

extern "C" void kernel_launch(void* const* d_in, const int* in_sizes, int n_in,
                              void* d_out, int out_size)
{
    const float* essays  = (const float*)d_in[0];
    const float* W_lstm  = (const float*)d_in[1];
    const float* b_lstm  = (const float*)d_in[2];
    const float* W_dense = (const float*)d_in[3];
    const float* b_dense = (const float*)d_in[4];
    float* out = (float*)d_out;

    const int smem_xp   = 150*32 * (int)sizeof(float);                 // 19,200 B
    const int smem_scan = (256*32 + 4*B_*EXS) * (int)sizeof(float);    // 53,248 B
    cudaFuncSetAttribute(xproj_kernel,
                         cudaFuncAttributeMaxDynamicSharedMemorySize, smem_xp);
    cudaFuncSetAttribute(lstm_scan_kernel,
                         cudaFuncAttributeMaxDynamicSharedMemorySize, smem_scan);

    transpose_kernel<<<T_, NTHR>>>(essays);
    xproj_kernel<<<1024, NTHR, smem_xp>>>(W_lstm, b_lstm);
    lstm_scan_kernel<<<NCTA, STHR, smem_scan>>>(W_lstm, W_dense, b_dense, out, 0);
    lstm_scan_kernel<<<NCTA, STHR, smem_scan>>>(W_lstm, W_dense, b_dense, out, SEGLEN);
}

// round 16
// speedup vs baseline: 2.2649x; 1.1600x over previous
#include <cuda_runtime.h>
#include <cstdint>

// Problem constants
#define B_     64
#define T_     1024
#define D_     300
#define H_     512
#define G_     (4*H_)      // 2048 gate columns
#define NCTA   128         // scan CTAs: each owns 4 h-cols -> 16 gate cols
#define NTHR   256         // xproj/transpose threads
#define STHR   512         // scan threads: 4 K-quarters x 4 warps
#define SEGLEN 512         // 2 scan segments
#define K4X    75          // D/4
#define EXS    20          // exchange row stride (floats)

// ---------------- device scratch (static) ----------------
__device__ float4 g_x2[(size_t)T_ * K4X * B_];        // essays transposed: [t][k4][m]
__device__ float4 g_h2[2][128 * B_];                  // h transposed: [buf][k4][m]
__device__ float  g_xp[(size_t)T_ * NCTA * B_ * 16];  // xproj[t][cc][m][16]
__device__ float  g_c [H_ * B_];                      // cell state [hcol*64+m]
__device__ float  g_hs[H_ * B_];                      // hsum
__device__ float  g_acc[B_];                          // dense partials
// 8 chunk generation counters, one 128B line each; monotonic, reset by finalize
__device__ __align__(128) unsigned g_ck[8 * 32];

// ---------------- packed fp32 (FFMA2) ----------------
__device__ __forceinline__ void ffma2(uint64_t& d, uint64_t a, uint64_t b) {
    asm volatile("fma.rn.f32x2 %0, %1, %2, %0;" : "+l"(d) : "l"(a), "l"(b));
}
__device__ __forceinline__ uint64_t pack2(float x, float y) {
    uint64_t r; asm("mov.b64 %0, {%1, %2};" : "=l"(r) : "f"(x), "f"(y)); return r;
}
__device__ __forceinline__ float2 unpack2(uint64_t v) {
    float2 f; asm("mov.b64 {%0, %1}, %2;" : "=f"(f.x), "=f"(f.y) : "l"(v)); return f;
}
__device__ __forceinline__ void lds_v2u64(uint64_t& a, uint64_t& b, unsigned addr) {
    asm volatile("ld.shared.v2.u64 {%0, %1}, [%2];" : "=l"(a), "=l"(b) : "r"(addr));
}
// ---------------- scoped atomics ----------------
__device__ __forceinline__ void atom_add_release_gpu(unsigned* p, unsigned v) {
    unsigned r;
    asm volatile("atom.release.gpu.global.add.u32 %0, [%1], %2;" : "=r"(r) : "l"(p), "r"(v) : "memory");
}
__device__ __forceinline__ unsigned ld_acquire_gpu(const unsigned* p) {
    unsigned r;
    asm volatile("ld.acquire.gpu.global.u32 %0, [%1];" : "=r"(r) : "l"(p) : "memory");
    return r;
}
__device__ __forceinline__ float sigm(float x)  { return 1.0f / (1.0f + __expf(-x)); }
__device__ __forceinline__ float tanh_f(float x){ return 2.0f * sigm(2.0f * x) - 1.0f; }

__device__ __forceinline__ void wait_chunk(int g, unsigned target) {
    while ((int)(ld_acquire_gpu(&g_ck[g * 32]) - target) < 0) { }
}

extern __shared__ float smem_dyn[];

// ============================================================================
// Phase 0: transpose essays -> g_x2[t][k4][m] float4   (verified)
// ============================================================================
__global__ void __launch_bounds__(NTHR)
transpose_kernel(const float* __restrict__ essays)
{
    const int t = blockIdx.x;
    for (int idx = threadIdx.x; idx < B_ * K4X; idx += NTHR) {
        int mm = idx / K4X, kk = idx - mm * K4X;
        float4 v = __ldcs((const float4*)(essays + ((size_t)mm * T_ + t) * D_) + kk);
        g_x2[((size_t)t * K4X + kk) * B_ + mm] = v;
    }
}

// ============================================================================
// Phase A: xproj (R15-verified, 2-row amortized)
// ============================================================================
__global__ void __launch_bounds__(NTHR, 4)
xproj_kernel(const float* __restrict__ W_lstm,
             const float* __restrict__ b_lstm)
{
    float* Wsm = smem_dyn;                   // [150 k-pairs][32] = 19,200 B
    const int tid  = threadIdx.x;
    const int cc   = blockIdx.x & 127;
    const int tch  = blockIdx.x >> 7;
    const int w    = tid >> 5;
    const int lane = tid & 31;
    const int tg   = w >> 2;
    const int wm   = w & 3;
    const int mpl  = lane & 7;
    const int ng   = lane >> 3;
    const int q0   = ng*4;
    const int mA   = wm*8 + mpl;

    for (int idx = tid; idx < D_*16; idx += NTHR) {
        int k = idx >> 4, c = idx & 15;
        int col = (c >> 2) * H_ + cc*4 + (c & 3);
        Wsm[((k >> 1)*16 + c)*2 + (k & 1)] = W_lstm[(size_t)k * G_ + col];
    }
    if (blockIdx.x == 0 && tid < B_) g_acc[tid] = 0.0f;
    __syncthreads();

    const int colb = ng*H_ + cc*4;
    const uint64_t b0 = pack2(b_lstm[colb+0], 0.0f);
    const uint64_t b1 = pack2(b_lstm[colb+1], 0.0f);
    const uint64_t b2 = pack2(b_lstm[colb+2], 0.0f);
    const uint64_t b3 = pack2(b_lstm[colb+3], 0.0f);

    const unsigned wb = (unsigned)__cvta_generic_to_shared(Wsm);
    const int tbeg = tch*128 + tg*64;

    for (int t = tbeg; t < tbeg + 64; t++) {
        uint64_t a0 = b0, a1 = b1, a2 = b2, a3 = b3;
        uint64_t a4 = b0, a5 = b1, a6 = b2, a7 = b3;
        const ulonglong2* xp = (const ulonglong2*)&g_x2[(size_t)t * K4X * B_];
        #pragma unroll 5
        for (int k4 = 0; k4 < K4X; k4++) {
            ulonglong2 aA = __ldcg(xp + k4*B_ + mA);
            ulonglong2 aB = __ldcg(xp + k4*B_ + mA + 32);
            unsigned wa = wb + (unsigned)k4*256u + (unsigned)q0*8u;
            uint64_t w0, w1, w2, w3;
            lds_v2u64(w0, w1, wa);       lds_v2u64(w2, w3, wa + 16);
            ffma2(a0, w0, aA.x); ffma2(a1, w1, aA.x); ffma2(a2, w2, aA.x); ffma2(a3, w3, aA.x);
            ffma2(a4, w0, aB.x); ffma2(a5, w1, aB.x); ffma2(a6, w2, aB.x); ffma2(a7, w3, aB.x);
            lds_v2u64(w0, w1, wa + 128); lds_v2u64(w2, w3, wa + 144);
            ffma2(a0, w0, aA.y); ffma2(a1, w1, aA.y); ffma2(a2, w2, aA.y); ffma2(a3, w3, aA.y);
            ffma2(a4, w0, aB.y); ffma2(a5, w1, aB.y); ffma2(a6, w2, aB.y); ffma2(a7, w3, aB.y);
        }
        float* dst = &g_xp[(((size_t)t*NCTA + cc)*B_)*16];
        {
            float2 u0 = unpack2(a0), u1 = unpack2(a1), u2 = unpack2(a2), u3 = unpack2(a3);
            *(float4*)(dst + (size_t)mA*16 + q0) =
                make_float4(u0.x+u0.y, u1.x+u1.y, u2.x+u2.y, u3.x+u3.y);
            float2 u4 = unpack2(a4), u5 = unpack2(a5), u6 = unpack2(a6), u7 = unpack2(a7);
            *(float4*)(dst + (size_t)(mA+32)*16 + q0) =
                make_float4(u4.x+u4.y, u5.x+u5.y, u6.x+u6.y, u7.x+u7.y);
        }
    }
}

// ============================================================================
// Phase B: scan segment [t0, t0+SEGLEN). 128 CTAs x 512 threads.
// Chunked dataflow sync: 8 h-chunks x 8 reducer-warp arrivals x 16 CTAs.
// GEMM warp kq self-polls only chunks {2kq, 2kq+1} -> arrival wave overlaps
// GEMM. One __syncthreads per step (ex partials). rounds0 = completed rounds
// at kernel entry (0 for seg0, SEGLEN+1 for seg1); counters are monotonic.
// ============================================================================
__global__ void __launch_bounds__(STHR, 1)
lstm_scan_kernel(const float* __restrict__ W_lstm,
                 const float* __restrict__ W_dense,
                 int t0, unsigned rounds0)
{
    float* Wsm = smem_dyn;              // [256 k-pairs][32] = 32,768 B
    float* ex  = smem_dyn + 256*32;     // 2 parity x 4 kq x [64][EXS] = 40,960 B

    const int tid   = threadIdx.x;
    const int cc    = blockIdx.x;
    const int w     = tid >> 5;
    const int lane  = tid & 31;
    const int kq    = w >> 2;            // K-quarter 0..3
    const int wq    = w & 3;
    const int mpl   = lane & 7;
    const int ng    = lane >> 3;
    const int q0    = ng*4;
    const int mA    = wq*8 + mpl;        // rows mA and mA+32
    const int t1    = t0 + SEGLEN;
    const bool last = (t1 == T_);
    const int mygrp = cc >> 4;           // this CTA's h-chunk group

    for (int idx = tid; idx < H_*16; idx += STHR) {
        int k = idx >> 4, c = idx & 15;
        int col = (c >> 2) * H_ + cc*4 + (c & 3);
        Wsm[((k >> 1)*16 + c)*2 + (k & 1)] = W_lstm[(size_t)(D_ + k) * G_ + col];
    }

    // reducer identity (tid < 256)
    const int rm   = (tid >> 5)*8 + (lane & 7);
    const int rng  = lane >> 3;
    const int hcol = cc*4 + rng;
    const int sidx = hcol*B_ + rm;

    float c_st = 0.0f, hsum = 0.0f;
    if (tid < 256) {
        if (t0 == 0) {
            if (rng == 0) g_h2[0][(cc << 6) + rm] = make_float4(0.f, 0.f, 0.f, 0.f);
        } else {
            c_st = g_c[sidx]; hsum = g_hs[sidx];
        }
    }

    const unsigned wbase = (unsigned)__cvta_generic_to_shared(Wsm);

    __syncthreads();                     // W loaded, init h stores issued

    // entry arrivals: 8 reducer warps publish initial state (release)
    if (tid < 256) {
        __syncwarp();
        if (lane == 0) atom_add_release_gpu(&g_ck[mygrp * 32], 1);
    }

    for (int i = 0; i < SEGLEN; i++) {
        const int t = t0 + i;
        const int p = i & 1;
        const unsigned target = 128u * (rounds0 + (unsigned)i + 1u);

        // prefetch xproj for kq==0 writers (independent of counters)
        float4 xpA = make_float4(0.f,0.f,0.f,0.f), xpB = xpA;
        if (kq == 0) {
            const float* xb = &g_xp[((size_t)t*NCTA + cc)*B_*16];
            xpA = __ldcg((const float4*)(xb + (size_t)mA*16 + q0));
            xpB = __ldcg((const float4*)(xb + (size_t)(mA+32)*16 + q0));
        }

        // GEMM: two 16-k4 halves, each gated by its chunk counter
        uint64_t p0=0,p1=0,p2=0,p3=0,p4=0,p5=0,p6=0,p7=0;
        const ulonglong2* hb = (const ulonglong2*)g_h2[t & 1];
        #pragma unroll 1
        for (int half = 0; half < 2; half++) {
            wait_chunk(2*kq + half, target);
            const int kb = (kq << 5) + (half << 4);
            #pragma unroll 8
            for (int ii = 0; ii < 16; ii++) {
                int k4 = kb + ii;
                ulonglong2 aA = __ldcg(hb + (k4 << 6) + mA);
                ulonglong2 aB = __ldcg(hb + (k4 << 6) + mA + 32);
                unsigned wa = wbase + (unsigned)k4*256u + (unsigned)q0*8u;
                uint64_t w0, w1, w2, w3;
                lds_v2u64(w0, w1, wa);       lds_v2u64(w2, w3, wa + 16);
                ffma2(p0, w0, aA.x); ffma2(p1, w1, aA.x); ffma2(p2, w2, aA.x); ffma2(p3, w3, aA.x);
                ffma2(p4, w0, aB.x); ffma2(p5, w1, aB.x); ffma2(p6, w2, aB.x); ffma2(p7, w3, aB.x);
                lds_v2u64(w0, w1, wa + 128); lds_v2u64(w2, w3, wa + 144);
                ffma2(p0, w0, aA.y); ffma2(p1, w1, aA.y); ffma2(p2, w2, aA.y); ffma2(p3, w3, aA.y);
                ffma2(p4, w0, aB.y); ffma2(p5, w1, aB.y); ffma2(p6, w2, aB.y); ffma2(p7, w3, aB.y);
            }
        }

        // write partials (kq0 folds xproj); ex[p][kq][m][c]
        float* exk = ex + (p*4 + kq) * (B_ * EXS);
        {
            float2 u0 = unpack2(p0), u1 = unpack2(p1), u2 = unpack2(p2), u3 = unpack2(p3);
            float2 u4 = unpack2(p4), u5 = unpack2(p5), u6 = unpack2(p6), u7 = unpack2(p7);
            *(float4*)&exk[mA*EXS + q0] =
                make_float4(u0.x+u0.y+xpA.x, u1.x+u1.y+xpA.y, u2.x+u2.y+xpA.z, u3.x+u3.y+xpA.w);
            *(float4*)&exk[(mA+32)*EXS + q0] =
                make_float4(u4.x+u4.y+xpB.x, u5.x+u5.y+xpB.y, u6.x+u6.y+xpB.z, u7.x+u7.y+xpB.w);
        }
        __syncthreads();                 // the ONE per-step CTA sync

        if (tid < 256) {
            const float* e0 = ex + (p*4 + 0) * (B_ * EXS);
            const float* e1 = ex + (p*4 + 1) * (B_ * EXS);
            const float* e2 = ex + (p*4 + 2) * (B_ * EXS);
            const float* e3 = ex + (p*4 + 3) * (B_ * EXS);
            int rb = rm*EXS;
            float gi = e0[rb+0*4+rng] + e1[rb+0*4+rng] + e2[rb+0*4+rng] + e3[rb+0*4+rng];
            float gj = e0[rb+1*4+rng] + e1[rb+1*4+rng] + e2[rb+1*4+rng] + e3[rb+1*4+rng];
            float gf = e0[rb+2*4+rng] + e1[rb+2*4+rng] + e2[rb+2*4+rng] + e3[rb+2*4+rng];
            float go = e0[rb+3*4+rng] + e1[rb+3*4+rng] + e2[rb+3*4+rng] + e3[rb+3*4+rng];

            float nc = c_st * sigm(gf + 1.0f) + sigm(gi) * tanh_f(gj);
            float nh = tanh_f(nc) * sigm(go);
            c_st = nc;
            hsum += nh;

            float s1 = __shfl_sync(0xffffffffu, nh, (lane & 7) + 8);
            float s2 = __shfl_sync(0xffffffffu, nh, (lane & 7) + 16);
            float s3 = __shfl_sync(0xffffffffu, nh, (lane & 7) + 24);
            if (rng == 0)
                g_h2[(t+1) & 1][(cc << 6) + rm] = make_float4(nh, s1, s2, s3);

            __syncwarp();                // warp-ordered h stores
            if (lane == 0) atom_add_release_gpu(&g_ck[mygrp * 32], 1);
        }
    }

    if (tid < 256) {
        if (!last) {
            g_c[sidx]  = c_st;
            g_hs[sidx] = hsum;
        } else {
            float part = hsum * (1.0f / (float)T_) * W_dense[hcol];
            part += __shfl_xor_sync(0xffffffffu, part, 8);
            part += __shfl_xor_sync(0xffffffffu, part, 16);
            if (lane < 8) atomicAdd(&g_acc[rm], part);
        }
    }
    // output + counter reset handled by finalize kernel (kernel-boundary order)
}

// ============================================================================
// Finalize: out = sigmoid(g_acc + b); reset chunk counters for next replay.
// ============================================================================
__global__ void __launch_bounds__(64)
finalize_kernel(const float* __restrict__ b_dense, float* __restrict__ out)
{
    int tid = threadIdx.x;
    if (tid < 8) g_ck[tid * 32] = 0u;
    out[tid] = 1.0f / (1.0f + expf(-(g_acc[tid] + b_dense[0])));
}

extern "C" void kernel_launch(void* const* d_in, const int* in_sizes, int n_in,
                              void* d_out, int out_size)
{
    const float* essays  = (const float*)d_in[0];
    const float* W_lstm  = (const float*)d_in[1];
    const float* b_lstm  = (const float*)d_in[2];
    const float* W_dense = (const float*)d_in[3];
    const float* b_dense = (const float*)d_in[4];
    float* out = (float*)d_out;

    const int smem_xp   = 150*32 * (int)sizeof(float);                   // 19,200 B
    const int smem_scan = (256*32 + 2*4*B_*EXS) * (int)sizeof(float);    // 73,728 B
    cudaFuncSetAttribute(xproj_kernel,
                         cudaFuncAttributeMaxDynamicSharedMemorySize, smem_xp);
    cudaFuncSetAttribute(lstm_scan_kernel,
                         cudaFuncAttributeMaxDynamicSharedMemorySize, smem_scan);

    transpose_kernel<<<T_, NTHR>>>(essays);
    xproj_kernel<<<1024, NTHR, smem_xp>>>(W_lstm, b_lstm);
    lstm_scan_kernel<<<NCTA, STHR, smem_scan>>>(W_lstm, W_dense, 0,      0u);
    lstm_scan_kernel<<<NCTA, STHR, smem_scan>>>(W_lstm, W_dense, SEGLEN, (unsigned)(SEGLEN + 1));
    finalize_kernel<<<1, 64>>>(b_dense, out);
}

// round 17
// speedup vs baseline: 2.4230x; 1.0698x over previous
#include <cuda_runtime.h>
#include <cstdint>

// Problem constants
#define B_     64
#define T_     1024
#define D_     300
#define H_     512
#define G_     (4*H_)      // 2048 gate columns
#define NCTA   128         // scan CTAs: each owns 4 h-cols -> 16 gate cols
#define NTHR   256         // xproj/transpose threads
#define STHR   256         // scan threads: 4 K-quarters x 2 warps
#define SEGLEN 512         // 2 scan segments
#define K4X    75          // D/4
#define EXS    20          // exchange row stride (floats)

// ---------------- device scratch (static) ----------------
__device__ float4 g_x2[(size_t)T_ * K4X * B_];        // essays transposed: [t][k4][m]
__device__ float4 g_h2[2][128 * B_];                  // h transposed: [buf][k4][m]
__device__ float  g_xp[(size_t)T_ * NCTA * B_ * 16];  // xproj[t][cc][m][16]
__device__ float  g_c [H_ * B_];                      // cell state [hcol*64+m]
__device__ float  g_hs[H_ * B_];                      // hsum
__device__ float  g_acc[B_];                          // dense partials
// 8 chunk generation counters, one 128B line each; monotonic, reset by finalize
__device__ __align__(128) unsigned g_ck[8 * 32];

// ---------------- packed fp32 (FFMA2) ----------------
__device__ __forceinline__ void ffma2(uint64_t& d, uint64_t a, uint64_t b) {
    asm volatile("fma.rn.f32x2 %0, %1, %2, %0;" : "+l"(d) : "l"(a), "l"(b));
}
__device__ __forceinline__ uint64_t pack2(float x, float y) {
    uint64_t r; asm("mov.b64 %0, {%1, %2};" : "=l"(r) : "f"(x), "f"(y)); return r;
}
__device__ __forceinline__ float2 unpack2(uint64_t v) {
    float2 f; asm("mov.b64 {%0, %1}, %2;" : "=f"(f.x), "=f"(f.y) : "l"(v)); return f;
}
__device__ __forceinline__ void lds_v2u64(uint64_t& a, uint64_t& b, unsigned addr) {
    asm volatile("ld.shared.v2.u64 {%0, %1}, [%2];" : "=l"(a), "=l"(b) : "r"(addr));
}
// ---------------- scoped atomics ----------------
__device__ __forceinline__ void atom_add_release_gpu(unsigned* p, unsigned v) {
    unsigned r;
    asm volatile("atom.release.gpu.global.add.u32 %0, [%1], %2;" : "=r"(r) : "l"(p), "r"(v) : "memory");
}
__device__ __forceinline__ unsigned ld_acquire_gpu(const unsigned* p) {
    unsigned r;
    asm volatile("ld.acquire.gpu.global.u32 %0, [%1];" : "=r"(r) : "l"(p) : "memory");
    return r;
}
__device__ __forceinline__ float sigm(float x)  { return 1.0f / (1.0f + __expf(-x)); }
__device__ __forceinline__ float tanh_f(float x){ return 2.0f * sigm(2.0f * x) - 1.0f; }

__device__ __forceinline__ void wait_chunk(int g, unsigned target) {
    while ((int)(ld_acquire_gpu(&g_ck[g * 32]) - target) < 0) { }
}

extern __shared__ float smem_dyn[];

// ============================================================================
// Phase 0: transpose essays -> g_x2[t][k4][m] float4   (verified)
// ============================================================================
__global__ void __launch_bounds__(NTHR)
transpose_kernel(const float* __restrict__ essays)
{
    const int t = blockIdx.x;
    for (int idx = threadIdx.x; idx < B_ * K4X; idx += NTHR) {
        int mm = idx / K4X, kk = idx - mm * K4X;
        float4 v = __ldcs((const float4*)(essays + ((size_t)mm * T_ + t) * D_) + kk);
        g_x2[((size_t)t * K4X + kk) * B_ + mm] = v;
    }
}

// ============================================================================
// Phase A: xproj[t][cc][m][c] = x_t[m] @ Wx[:, col(cc,c)] + b
// 4-row x 4-col thread tiles: each W LDS feeds 32 FFMA2.
// ============================================================================
__global__ void __launch_bounds__(NTHR, 4)
xproj_kernel(const float* __restrict__ W_lstm,
             const float* __restrict__ b_lstm)
{
    float* Wsm = smem_dyn;                   // [150 k-pairs][32] = 19,200 B
    const int tid  = threadIdx.x;
    const int cc   = blockIdx.x & 127;
    const int tch  = blockIdx.x >> 7;        // 0..7, 128 t each
    const int w    = tid >> 5;
    const int lane = tid & 31;
    const int tg   = w >> 1;                 // t-subgroup 0..3 (32 t each)
    const int mpl  = lane & 7;
    const int ng   = lane >> 3;
    const int q0   = ng*4;
    const int mA   = (w & 1)*8 + mpl;        // rows mA, +16, +32, +48

    for (int idx = tid; idx < D_*16; idx += NTHR) {
        int k = idx >> 4, c = idx & 15;
        int col = (c >> 2) * H_ + cc*4 + (c & 3);
        Wsm[((k >> 1)*16 + c)*2 + (k & 1)] = W_lstm[(size_t)k * G_ + col];
    }
    if (blockIdx.x == 0 && tid < B_) g_acc[tid] = 0.0f;
    __syncthreads();

    const int colb = ng*H_ + cc*4;
    uint64_t bias[4];
    #pragma unroll
    for (int c = 0; c < 4; c++) bias[c] = pack2(b_lstm[colb + c], 0.0f);

    const unsigned wb = (unsigned)__cvta_generic_to_shared(Wsm);
    const int tbeg = tch*128 + tg*32;

    for (int t = tbeg; t < tbeg + 32; t++) {
        uint64_t acc[4][4];
        #pragma unroll
        for (int r = 0; r < 4; r++)
            #pragma unroll
            for (int c = 0; c < 4; c++) acc[r][c] = bias[c];

        const ulonglong2* xp = (const ulonglong2*)&g_x2[(size_t)t * K4X * B_];
        #pragma unroll 5
        for (int k4 = 0; k4 < K4X; k4++) {
            const ulonglong2* xr = xp + k4*B_;
            ulonglong2 aA = __ldcg(xr + mA);
            ulonglong2 aB = __ldcg(xr + mA + 16);
            ulonglong2 aC = __ldcg(xr + mA + 32);
            ulonglong2 aD = __ldcg(xr + mA + 48);
            unsigned wa = wb + (unsigned)k4*256u + (unsigned)q0*8u;
            uint64_t w0, w1, w2, w3;
            lds_v2u64(w0, w1, wa);       lds_v2u64(w2, w3, wa + 16);
            ffma2(acc[0][0],w0,aA.x); ffma2(acc[0][1],w1,aA.x); ffma2(acc[0][2],w2,aA.x); ffma2(acc[0][3],w3,aA.x);
            ffma2(acc[1][0],w0,aB.x); ffma2(acc[1][1],w1,aB.x); ffma2(acc[1][2],w2,aB.x); ffma2(acc[1][3],w3,aB.x);
            ffma2(acc[2][0],w0,aC.x); ffma2(acc[2][1],w1,aC.x); ffma2(acc[2][2],w2,aC.x); ffma2(acc[2][3],w3,aC.x);
            ffma2(acc[3][0],w0,aD.x); ffma2(acc[3][1],w1,aD.x); ffma2(acc[3][2],w2,aD.x); ffma2(acc[3][3],w3,aD.x);
            lds_v2u64(w0, w1, wa + 128); lds_v2u64(w2, w3, wa + 144);
            ffma2(acc[0][0],w0,aA.y); ffma2(acc[0][1],w1,aA.y); ffma2(acc[0][2],w2,aA.y); ffma2(acc[0][3],w3,aA.y);
            ffma2(acc[1][0],w0,aB.y); ffma2(acc[1][1],w1,aB.y); ffma2(acc[1][2],w2,aB.y); ffma2(acc[1][3],w3,aB.y);
            ffma2(acc[2][0],w0,aC.y); ffma2(acc[2][1],w1,aC.y); ffma2(acc[2][2],w2,aC.y); ffma2(acc[2][3],w3,aC.y);
            ffma2(acc[3][0],w0,aD.y); ffma2(acc[3][1],w1,aD.y); ffma2(acc[3][2],w2,aD.y); ffma2(acc[3][3],w3,aD.y);
        }
        float* dst = &g_xp[(((size_t)t*NCTA + cc)*B_)*16];
        #pragma unroll
        for (int r = 0; r < 4; r++) {
            float2 u0 = unpack2(acc[r][0]), u1 = unpack2(acc[r][1]);
            float2 u2 = unpack2(acc[r][2]), u3 = unpack2(acc[r][3]);
            *(float4*)(dst + (size_t)(mA + 16*r)*16 + q0) =
                make_float4(u0.x+u0.y, u1.x+u1.y, u2.x+u2.y, u3.x+u3.y);
        }
    }
}

// ============================================================================
// Phase B: scan segment [t0, t0+SEGLEN). 128 CTAs x 256 threads.
// 4-row x 4-col thread tiles over a K-quarter; chunked dataflow sync (R16).
// ============================================================================
__global__ void __launch_bounds__(STHR, 1)
lstm_scan_kernel(const float* __restrict__ W_lstm,
                 const float* __restrict__ W_dense,
                 int t0, unsigned rounds0)
{
    float* Wsm = smem_dyn;              // [256 k-pairs][32] = 32,768 B
    float* ex  = smem_dyn + 256*32;     // 2 parity x 4 kq x [64][EXS] = 40,960 B

    const int tid   = threadIdx.x;
    const int cc    = blockIdx.x;
    const int w     = tid >> 5;
    const int lane  = tid & 31;
    const int kq    = w >> 1;            // K-quarter 0..3
    const int mpl   = lane & 7;
    const int ng    = lane >> 3;
    const int q0    = ng*4;
    const int mA    = (w & 1)*8 + mpl;   // rows mA, +16, +32, +48
    const int t1    = t0 + SEGLEN;
    const bool last = (t1 == T_);
    const int mygrp = cc >> 4;           // this CTA's h-chunk group

    for (int idx = tid; idx < H_*16; idx += STHR) {
        int k = idx >> 4, c = idx & 15;
        int col = (c >> 2) * H_ + cc*4 + (c & 3);
        Wsm[((k >> 1)*16 + c)*2 + (k & 1)] = W_lstm[(size_t)(D_ + k) * G_ + col];
    }

    // reducer identity (all 256 threads)
    const int rm   = w*8 + mpl;
    const int rng  = ng;
    const int hcol = cc*4 + rng;
    const int sidx = hcol*B_ + rm;

    float c_st = 0.0f, hsum = 0.0f;
    if (t0 == 0) {
        if (rng == 0) g_h2[0][(cc << 6) + rm] = make_float4(0.f, 0.f, 0.f, 0.f);
    } else {
        c_st = g_c[sidx]; hsum = g_hs[sidx];
    }

    const unsigned wbase = (unsigned)__cvta_generic_to_shared(Wsm);

    __syncthreads();                     // W loaded, init h stores issued

    // entry arrivals: 8 warps publish initial state (release)
    __syncwarp();
    if (lane == 0) atom_add_release_gpu(&g_ck[mygrp * 32], 1);

    for (int i = 0; i < SEGLEN; i++) {
        const int t = t0 + i;
        const int p = i & 1;
        const unsigned target = 128u * (rounds0 + (unsigned)i + 1u);

        // prefetch xproj for kq==0 writers (independent of counters)
        float4 xp0 = make_float4(0.f,0.f,0.f,0.f), xp1 = xp0, xp2 = xp0, xp3 = xp0;
        if (kq == 0) {
            const float* xb = &g_xp[((size_t)t*NCTA + cc)*B_*16];
            xp0 = __ldcg((const float4*)(xb + (size_t)(mA     )*16 + q0));
            xp1 = __ldcg((const float4*)(xb + (size_t)(mA + 16)*16 + q0));
            xp2 = __ldcg((const float4*)(xb + (size_t)(mA + 32)*16 + q0));
            xp3 = __ldcg((const float4*)(xb + (size_t)(mA + 48)*16 + q0));
        }

        // GEMM: two 16-k4 halves, each gated by its chunk counter
        uint64_t acc[4][4];
        #pragma unroll
        for (int r = 0; r < 4; r++)
            #pragma unroll
            for (int c = 0; c < 4; c++) acc[r][c] = 0ull;

        const ulonglong2* hb = (const ulonglong2*)g_h2[t & 1];
        #pragma unroll 1
        for (int half = 0; half < 2; half++) {
            wait_chunk(2*kq + half, target);
            const int kb = (kq << 5) + (half << 4);
            #pragma unroll 8
            for (int ii = 0; ii < 16; ii++) {
                int k4 = kb + ii;
                const ulonglong2* hr = hb + (k4 << 6);
                ulonglong2 aA = __ldcg(hr + mA);
                ulonglong2 aB = __ldcg(hr + mA + 16);
                ulonglong2 aC = __ldcg(hr + mA + 32);
                ulonglong2 aD = __ldcg(hr + mA + 48);
                unsigned wa = wbase + (unsigned)k4*256u + (unsigned)q0*8u;
                uint64_t w0, w1, w2, w3;
                lds_v2u64(w0, w1, wa);       lds_v2u64(w2, w3, wa + 16);
                ffma2(acc[0][0],w0,aA.x); ffma2(acc[0][1],w1,aA.x); ffma2(acc[0][2],w2,aA.x); ffma2(acc[0][3],w3,aA.x);
                ffma2(acc[1][0],w0,aB.x); ffma2(acc[1][1],w1,aB.x); ffma2(acc[1][2],w2,aB.x); ffma2(acc[1][3],w3,aB.x);
                ffma2(acc[2][0],w0,aC.x); ffma2(acc[2][1],w1,aC.x); ffma2(acc[2][2],w2,aC.x); ffma2(acc[2][3],w3,aC.x);
                ffma2(acc[3][0],w0,aD.x); ffma2(acc[3][1],w1,aD.x); ffma2(acc[3][2],w2,aD.x); ffma2(acc[3][3],w3,aD.x);
                lds_v2u64(w0, w1, wa + 128); lds_v2u64(w2, w3, wa + 144);
                ffma2(acc[0][0],w0,aA.y); ffma2(acc[0][1],w1,aA.y); ffma2(acc[0][2],w2,aA.y); ffma2(acc[0][3],w3,aA.y);
                ffma2(acc[1][0],w0,aB.y); ffma2(acc[1][1],w1,aB.y); ffma2(acc[1][2],w2,aB.y); ffma2(acc[1][3],w3,aB.y);
                ffma2(acc[2][0],w0,aC.y); ffma2(acc[2][1],w1,aC.y); ffma2(acc[2][2],w2,aC.y); ffma2(acc[2][3],w3,aC.y);
                ffma2(acc[3][0],w0,aD.y); ffma2(acc[3][1],w1,aD.y); ffma2(acc[3][2],w2,aD.y); ffma2(acc[3][3],w3,aD.y);
            }
        }

        // write partials (kq0 folds xproj); ex[p][kq][m][c]
        float* exk = ex + (p*4 + kq) * (B_ * EXS);
        {
            float2 u0, u1, u2, u3;
            u0 = unpack2(acc[0][0]); u1 = unpack2(acc[0][1]); u2 = unpack2(acc[0][2]); u3 = unpack2(acc[0][3]);
            *(float4*)&exk[(mA     )*EXS + q0] =
                make_float4(u0.x+u0.y+xp0.x, u1.x+u1.y+xp0.y, u2.x+u2.y+xp0.z, u3.x+u3.y+xp0.w);
            u0 = unpack2(acc[1][0]); u1 = unpack2(acc[1][1]); u2 = unpack2(acc[1][2]); u3 = unpack2(acc[1][3]);
            *(float4*)&exk[(mA + 16)*EXS + q0] =
                make_float4(u0.x+u0.y+xp1.x, u1.x+u1.y+xp1.y, u2.x+u2.y+xp1.z, u3.x+u3.y+xp1.w);
            u0 = unpack2(acc[2][0]); u1 = unpack2(acc[2][1]); u2 = unpack2(acc[2][2]); u3 = unpack2(acc[2][3]);
            *(float4*)&exk[(mA + 32)*EXS + q0] =
                make_float4(u0.x+u0.y+xp2.x, u1.x+u1.y+xp2.y, u2.x+u2.y+xp2.z, u3.x+u3.y+xp2.w);
            u0 = unpack2(acc[3][0]); u1 = unpack2(acc[3][1]); u2 = unpack2(acc[3][2]); u3 = unpack2(acc[3][3]);
            *(float4*)&exk[(mA + 48)*EXS + q0] =
                make_float4(u0.x+u0.y+xp3.x, u1.x+u1.y+xp3.y, u2.x+u2.y+xp3.z, u3.x+u3.y+xp3.w);
        }
        __syncthreads();                 // the ONE per-step CTA sync

        {
            const float* e0 = ex + (p*4 + 0) * (B_ * EXS);
            const float* e1 = ex + (p*4 + 1) * (B_ * EXS);
            const float* e2 = ex + (p*4 + 2) * (B_ * EXS);
            const float* e3 = ex + (p*4 + 3) * (B_ * EXS);
            int rb = rm*EXS;
            float gi = e0[rb+0*4+rng] + e1[rb+0*4+rng] + e2[rb+0*4+rng] + e3[rb+0*4+rng];
            float gj = e0[rb+1*4+rng] + e1[rb+1*4+rng] + e2[rb+1*4+rng] + e3[rb+1*4+rng];
            float gf = e0[rb+2*4+rng] + e1[rb+2*4+rng] + e2[rb+2*4+rng] + e3[rb+2*4+rng];
            float go = e0[rb+3*4+rng] + e1[rb+3*4+rng] + e2[rb+3*4+rng] + e3[rb+3*4+rng];

            float nc = c_st * sigm(gf + 1.0f) + sigm(gi) * tanh_f(gj);
            float nh = tanh_f(nc) * sigm(go);
            c_st = nc;
            hsum += nh;

            float s1 = __shfl_sync(0xffffffffu, nh, (lane & 7) + 8);
            float s2 = __shfl_sync(0xffffffffu, nh, (lane & 7) + 16);
            float s3 = __shfl_sync(0xffffffffu, nh, (lane & 7) + 24);
            if (rng == 0)
                g_h2[(t+1) & 1][(cc << 6) + rm] = make_float4(nh, s1, s2, s3);

            __syncwarp();                // warp-ordered h stores
            if (lane == 0) atom_add_release_gpu(&g_ck[mygrp * 32], 1);
        }
    }

    if (!last) {
        g_c[sidx]  = c_st;
        g_hs[sidx] = hsum;
    } else {
        float part = hsum * (1.0f / (float)T_) * W_dense[hcol];
        part += __shfl_xor_sync(0xffffffffu, part, 8);
        part += __shfl_xor_sync(0xffffffffu, part, 16);
        if (lane < 8) atomicAdd(&g_acc[rm], part);
    }
    // output + counter reset handled by finalize kernel (kernel-boundary order)
}

// ============================================================================
// Finalize: out = sigmoid(g_acc + b); reset chunk counters for next replay.
// ============================================================================
__global__ void __launch_bounds__(64)
finalize_kernel(const float* __restrict__ b_dense, float* __restrict__ out)
{
    int tid = threadIdx.x;
    if (tid < 8) g_ck[tid * 32] = 0u;
    out[tid] = 1.0f / (1.0f + expf(-(g_acc[tid] + b_dense[0])));
}

extern "C" void kernel_launch(void* const* d_in, const int* in_sizes, int n_in,
                              void* d_out, int out_size)
{
    const float* essays  = (const float*)d_in[0];
    const float* W_lstm  = (const float*)d_in[1];
    const float* b_lstm  = (const float*)d_in[2];
    const float* W_dense = (const float*)d_in[3];
    const float* b_dense = (const float*)d_in[4];
    float* out = (float*)d_out;

    const int smem_xp   = 150*32 * (int)sizeof(float);                   // 19,200 B
    const int smem_scan = (256*32 + 2*4*B_*EXS) * (int)sizeof(float);    // 73,728 B
    cudaFuncSetAttribute(xproj_kernel,
                         cudaFuncAttributeMaxDynamicSharedMemorySize, smem_xp);
    cudaFuncSetAttribute(lstm_scan_kernel,
                         cudaFuncAttributeMaxDynamicSharedMemorySize, smem_scan);

    transpose_kernel<<<T_, NTHR>>>(essays);
    xproj_kernel<<<1024, NTHR, smem_xp>>>(W_lstm, b_lstm);
    lstm_scan_kernel<<<NCTA, STHR, smem_scan>>>(W_lstm, W_dense, 0,      0u);
    lstm_scan_kernel<<<NCTA, STHR, smem_scan>>>(W_lstm, W_dense, SEGLEN, (unsigned)(SEGLEN + 1));
    finalize_kernel<<<1, 64>>>(b_dense, out);
}